// round 4
// baseline (speedup 1.0000x reference)
#include <cuda_runtime.h>
#include <math.h>

#define BATCH  16
#define SEQ    512
#define DMODEL 768
#define NHEAD  12
#define DHEAD  64
#define NDIST  32

// ---------------- scratch (static device memory; referenced by symbol only) ----------------
__device__ float g_x  [BATCH*SEQ*DMODEL];
__device__ float g_q  [BATCH*SEQ*DMODEL];   // layout (B,H,N,DK)
__device__ float g_k  [BATCH*SEQ*DMODEL];   // layout (B,H,N,DK)
__device__ float g_v  [BATCH*SEQ*DMODEL];   // layout (B,H,N,DK)
__device__ float g_ctx[BATCH*SEQ*DMODEL];   // layout (B,N,H*DK)
__device__ int   g_px [BATCH*SEQ];
__device__ int   g_py [BATCH*SEQ];

// ---------------- LayerNorm: one block per token row, writes g_x ----------------
__global__ __launch_bounds__(256) void ln_kernel(
    const float* __restrict__ feat,
    const float* __restrict__ gamma,
    const float* __restrict__ beta)
{
    int row = blockIdx.x;
    const float* x = feat + (size_t)row * DMODEL;
    float* y = g_x + (size_t)row * DMODEL;
    int t = threadIdx.x;

    float v0 = x[t], v1 = x[t + 256], v2 = x[t + 512];
    float s  = v0 + v1 + v2;
    float q  = v0*v0 + v1*v1 + v2*v2;

    __shared__ float ss[8], sq[8];
    #pragma unroll
    for (int o = 16; o > 0; o >>= 1) {
        s += __shfl_xor_sync(0xffffffffu, s, o);
        q += __shfl_xor_sync(0xffffffffu, q, o);
    }
    if ((t & 31) == 0) { ss[t >> 5] = s; sq[t >> 5] = q; }
    __syncthreads();
    if (t == 0) {
        float a = 0.f, b2 = 0.f;
        #pragma unroll
        for (int i = 0; i < 8; i++) { a += ss[i]; b2 += sq[i]; }
        ss[0] = a; sq[0] = b2;
    }
    __syncthreads();
    float mean = ss[0] * (1.0f / DMODEL);
    float var  = sq[0] * (1.0f / DMODEL) - mean * mean;
    float inv  = rsqrtf(var + 1e-5f);

    y[t]       = (v0 - mean) * inv * gamma[t]       + beta[t];
    y[t + 256] = (v1 - mean) * inv * gamma[t + 256] + beta[t + 256];
    y[t + 512] = (v2 - mean) * inv * gamma[t + 512] + beta[t + 512];
}

// ---------------- patch bins (exact replica of reference semantics), writes g_px/g_py ----------------
__global__ void bins_kernel(
    const float* __restrict__ boxes,
    const int* __restrict__ image_sizes)
{
    int idx = blockIdx.x * blockDim.x + threadIdx.x;
    if (idx >= BATCH * SEQ) return;
    int b = idx / SEQ;
    float w = (float)image_sizes[b * 4 + 0];
    float h = (float)image_sizes[b * 4 + 1];
    const float* bx = boxes + (size_t)idx * 4;
    float x0 = bx[0] * w, y0 = bx[1] * h, x1 = bx[2] * w, y1 = bx[3] * h;
    float spaw = floorf(w / 11.0f);
    float spah = floorf(h / 11.0f);
    float cx = floorf((x0 + x1) / 2.0f);
    float cy = floorf((y0 + y1) / 2.0f);
    // argmax over boolean mask -> FIRST j where lb<=c<=hb, default 0
    int pxv = 0, pyv = 0;
    for (int j = 10; j >= 0; j--) {
        float lbw = (float)j * spaw, hbw = (float)(j + 1) * spaw;
        if (lbw <= cx && cx <= hbw) pxv = j;
        float lbh = (float)j * spah, hbh = (float)(j + 1) * spah;
        if (lbh <= cy && cy <= hbh) pyv = j;
    }
    g_px[idx] = pxv;
    g_py[idx] = pyv;
}

// ---------------- NT GEMM: C[m][n] = dot(A[m,:], W[n,:]) + bias[n] ----------------
// 128x128 tile, BK=16, 256 threads, 8x8 micro-tile. M=8192, N=K=768 fixed.
// MODE 0: A=g_ctx, write row-major to Cout arg.
// MODE 1/2/3: A=g_x, scatter into g_q/g_k/g_v as (B,H,N,DK).
template<int MODE>
__global__ __launch_bounds__(256) void gemm_nt128(
    const float* __restrict__ W,
    const float* __restrict__ bias,
    float* __restrict__ Cout)
{
    const float* A = (MODE == 0) ? g_ctx : g_x;
    const int K = DMODEL;

    __shared__ float As[16][132];
    __shared__ float Bs[16][132];
    const int t  = threadIdx.x;
    const int tx = t & 15, ty = t >> 4;
    const int row0 = blockIdx.y * 128, col0 = blockIdx.x * 128;
    const int lr = t >> 1;            // 0..127
    const int lc = (t & 1) * 8;       // 0 or 8
    const float* Ap = A + (size_t)(row0 + lr) * K + lc;
    const float* Wp = W + (size_t)(col0 + lr) * K + lc;

    float acc[8][8];
    #pragma unroll
    for (int i = 0; i < 8; i++)
        #pragma unroll
        for (int j = 0; j < 8; j++) acc[i][j] = 0.f;

    for (int k0 = 0; k0 < K; k0 += 16) {
        float4 a0 = *(const float4*)(Ap + k0);
        float4 a1 = *(const float4*)(Ap + k0 + 4);
        float4 b0 = *(const float4*)(Wp + k0);
        float4 b1 = *(const float4*)(Wp + k0 + 4);
        __syncthreads();
        As[lc + 0][lr] = a0.x; As[lc + 1][lr] = a0.y; As[lc + 2][lr] = a0.z; As[lc + 3][lr] = a0.w;
        As[lc + 4][lr] = a1.x; As[lc + 5][lr] = a1.y; As[lc + 6][lr] = a1.z; As[lc + 7][lr] = a1.w;
        Bs[lc + 0][lr] = b0.x; Bs[lc + 1][lr] = b0.y; Bs[lc + 2][lr] = b0.z; Bs[lc + 3][lr] = b0.w;
        Bs[lc + 4][lr] = b1.x; Bs[lc + 5][lr] = b1.y; Bs[lc + 6][lr] = b1.z; Bs[lc + 7][lr] = b1.w;
        __syncthreads();
        #pragma unroll
        for (int kk = 0; kk < 16; kk++) {
            float4 av0 = *(const float4*)&As[kk][ty * 8];
            float4 av1 = *(const float4*)&As[kk][ty * 8 + 4];
            float4 bv0 = *(const float4*)&Bs[kk][tx * 8];
            float4 bv1 = *(const float4*)&Bs[kk][tx * 8 + 4];
            float a[8]  = {av0.x, av0.y, av0.z, av0.w, av1.x, av1.y, av1.z, av1.w};
            float bb[8] = {bv0.x, bv0.y, bv0.z, bv0.w, bv1.x, bv1.y, bv1.z, bv1.w};
            #pragma unroll
            for (int i = 0; i < 8; i++)
                #pragma unroll
                for (int j = 0; j < 8; j++)
                    acc[i][j] = fmaf(a[i], bb[j], acc[i][j]);
        }
    }

    float* Cdst = (MODE == 0) ? Cout : (MODE == 1) ? g_q : (MODE == 2) ? g_k : g_v;
    #pragma unroll
    for (int i = 0; i < 8; i++) {
        int m = row0 + ty * 8 + i;
        #pragma unroll
        for (int j = 0; j < 8; j++) {
            int n = col0 + tx * 8 + j;
            float v = acc[i][j] + bias[n];
            if (MODE == 0) {
                Cdst[(size_t)m * DMODEL + n] = v;
            } else {
                int b  = m >> 9;       // SEQ = 512
                int nq = m & 511;
                int hh = n >> 6;       // DHEAD = 64
                int dk = n & 63;
                Cdst[(((size_t)(b * NHEAD + hh)) * SEQ + nq) * DHEAD + dk] = v;
            }
        }
    }
}

// ---------------- attention scores: S = QK^T/8 + dist_bias ----------------
// grid (ktile=8, qtile=8, bh=192); 64x64 output tile, full DK=64 in one pass.
__global__ __launch_bounds__(256) void attn_scores(
    const float* __restrict__ dist_emb, float* __restrict__ att)
{
    int bh = blockIdx.z;
    int b  = bh / NHEAD, h = bh % NHEAD;
    int q0 = blockIdx.y * 64, k0v = blockIdx.x * 64;

    __shared__ float Qs[64][68];
    __shared__ float Ks[64][68];
    __shared__ float emb[NDIST];
    __shared__ int   spx[2][64], spy[2][64];   // [0]=queries, [1]=keys

    const float* Qb = g_q + (size_t)bh * SEQ * DHEAD;
    const float* Kb = g_k + (size_t)bh * SEQ * DHEAD;
    int t  = threadIdx.x;
    int lr = t >> 2;            // 0..63
    int lc = (t & 3) * 16;      // 0,16,32,48
    {
        const float* qp = Qb + (size_t)(q0 + lr) * DHEAD + lc;
        const float* kp = Kb + (size_t)(k0v + lr) * DHEAD + lc;
        #pragma unroll
        for (int u = 0; u < 4; u++) {
            float4 v = *(const float4*)(qp + u * 4);
            Qs[lc + u*4 + 0][lr] = v.x; Qs[lc + u*4 + 1][lr] = v.y;
            Qs[lc + u*4 + 2][lr] = v.z; Qs[lc + u*4 + 3][lr] = v.w;
            float4 w = *(const float4*)(kp + u * 4);
            Ks[lc + u*4 + 0][lr] = w.x; Ks[lc + u*4 + 1][lr] = w.y;
            Ks[lc + u*4 + 2][lr] = w.z; Ks[lc + u*4 + 3][lr] = w.w;
        }
    }
    if (t < NDIST) emb[t] = dist_emb[t * NHEAD + h];
    if (t < 64) {
        spx[0][t] = g_px[b * SEQ + q0 + t];
        spy[0][t] = g_py[b * SEQ + q0 + t];
    } else if (t < 128) {
        int u = t - 64;
        spx[1][u] = g_px[b * SEQ + k0v + u];
        spy[1][u] = g_py[b * SEQ + k0v + u];
    }
    __syncthreads();

    int tx = t & 15, ty = t >> 4;
    float acc[4][4];
    #pragma unroll
    for (int i = 0; i < 4; i++)
        #pragma unroll
        for (int j = 0; j < 4; j++) acc[i][j] = 0.f;

    #pragma unroll 8
    for (int kk = 0; kk < 64; kk++) {
        float4 av = *(const float4*)&Qs[kk][ty * 4];
        float4 bv = *(const float4*)&Ks[kk][tx * 4];
        float a[4]  = {av.x, av.y, av.z, av.w};
        float bb[4] = {bv.x, bv.y, bv.z, bv.w};
        #pragma unroll
        for (int i = 0; i < 4; i++)
            #pragma unroll
            for (int j = 0; j < 4; j++)
                acc[i][j] = fmaf(a[i], bb[j], acc[i][j]);
    }

    float* outp = att + ((size_t)bh * SEQ + q0) * SEQ + k0v;
    #pragma unroll
    for (int i = 0; i < 4; i++) {
        int qi = ty * 4 + i;
        #pragma unroll
        for (int j = 0; j < 4; j++) {
            int kj = tx * 4 + j;
            int dx = spx[1][kj] - spx[0][qi];
            int dy = spy[1][kj] - spy[0][qi];
            int bin = (int)(sqrtf((float)(dx * dx + dy * dy)) * 2.0f);
            outp[(size_t)qi * SEQ + kj] = acc[i][j] * 0.125f + emb[bin];
        }
    }
}

// ---------------- row softmax over 512 keys (in place) ----------------
__global__ __launch_bounds__(128) void softmax_rows(float* __restrict__ att)
{
    size_t row = blockIdx.x;                 // B*H*N rows
    float* p = att + row * SEQ;
    int t = threadIdx.x;
    float4 v = ((float4*)p)[t];              // 128 threads * 4 = 512

    __shared__ float red[4];
    float m = fmaxf(fmaxf(v.x, v.y), fmaxf(v.z, v.w));
    #pragma unroll
    for (int o = 16; o > 0; o >>= 1) m = fmaxf(m, __shfl_xor_sync(0xffffffffu, m, o));
    if ((t & 31) == 0) red[t >> 5] = m;
    __syncthreads();
    m = fmaxf(fmaxf(red[0], red[1]), fmaxf(red[2], red[3]));
    __syncthreads();

    float e0 = expf(v.x - m), e1 = expf(v.y - m), e2 = expf(v.z - m), e3 = expf(v.w - m);
    float s = e0 + e1 + e2 + e3;
    #pragma unroll
    for (int o = 16; o > 0; o >>= 1) s += __shfl_xor_sync(0xffffffffu, s, o);
    if ((t & 31) == 0) red[t >> 5] = s;
    __syncthreads();
    s = red[0] + red[1] + red[2] + red[3];
    float inv = 1.0f / s;

    float4 r = make_float4(e0 * inv, e1 * inv, e2 * inv, e3 * inv);
    ((float4*)p)[t] = r;
}

// ---------------- PV: g_ctx[b,q,h*64+d] = sum_k att[b,h,q,k] * g_v[b,h,k,d] ----------------
// grid (1, qtile=8, bh=192); BM=64 queries, BN=64=DK, BK=32.
__global__ __launch_bounds__(256) void attn_pv(const float* __restrict__ att)
{
    int bh = blockIdx.z;
    int b  = bh / NHEAD, h = bh % NHEAD;
    int q0 = blockIdx.y * 64;

    __shared__ float Ps[32][68];
    __shared__ float Vs[32][68];
    const float* Pb = att + ((size_t)bh * SEQ + q0) * SEQ;
    const float* Vb = g_v + (size_t)bh * SEQ * DHEAD;

    int t  = threadIdx.x;
    int tx = t & 15, ty = t >> 4;
    int pr = t >> 2, pc = (t & 3) * 8;   // P tile: 64 rows x 32 cols
    int vr = t >> 3, vc = (t & 7) * 8;   // V tile: 32 rows x 64 cols

    float acc[4][4];
    #pragma unroll
    for (int i = 0; i < 4; i++)
        #pragma unroll
        for (int j = 0; j < 4; j++) acc[i][j] = 0.f;

    for (int k0 = 0; k0 < SEQ; k0 += 32) {
        float4 p0 = *(const float4*)(Pb + (size_t)pr * SEQ + k0 + pc);
        float4 p1 = *(const float4*)(Pb + (size_t)pr * SEQ + k0 + pc + 4);
        float4 v0 = *(const float4*)(Vb + (size_t)(k0 + vr) * DHEAD + vc);
        float4 v1 = *(const float4*)(Vb + (size_t)(k0 + vr) * DHEAD + vc + 4);
        __syncthreads();
        Ps[pc + 0][pr] = p0.x; Ps[pc + 1][pr] = p0.y; Ps[pc + 2][pr] = p0.z; Ps[pc + 3][pr] = p0.w;
        Ps[pc + 4][pr] = p1.x; Ps[pc + 5][pr] = p1.y; Ps[pc + 6][pr] = p1.z; Ps[pc + 7][pr] = p1.w;
        Vs[vr][vc + 0] = v0.x; Vs[vr][vc + 1] = v0.y; Vs[vr][vc + 2] = v0.z; Vs[vr][vc + 3] = v0.w;
        Vs[vr][vc + 4] = v1.x; Vs[vr][vc + 5] = v1.y; Vs[vr][vc + 6] = v1.z; Vs[vr][vc + 7] = v1.w;
        __syncthreads();
        #pragma unroll 8
        for (int kk = 0; kk < 32; kk++) {
            float4 av = *(const float4*)&Ps[kk][ty * 4];
            float4 bv = *(const float4*)&Vs[kk][tx * 4];
            float a[4]  = {av.x, av.y, av.z, av.w};
            float bb[4] = {bv.x, bv.y, bv.z, bv.w};
            #pragma unroll
            for (int i = 0; i < 4; i++)
                #pragma unroll
                for (int j = 0; j < 4; j++)
                    acc[i][j] = fmaf(a[i], bb[j], acc[i][j]);
        }
    }

    #pragma unroll
    for (int i = 0; i < 4; i++) {
        int q = q0 + ty * 4 + i;
        #pragma unroll
        for (int j = 0; j < 4; j++) {
            int d = tx * 4 + j;
            g_ctx[((size_t)(b * SEQ + q)) * DMODEL + h * DHEAD + d] = acc[i][j];
        }
    }
}

// ---------------- launch: pure kernel launches, no other runtime API ----------------
extern "C" void kernel_launch(void* const* d_in, const int* in_sizes, int n_in,
                              void* d_out, int out_size)
{
    const float* features    = (const float*)d_in[0];
    const float* boxes       = (const float*)d_in[1];
    const int*   image_sizes = (const int*)  d_in[2];
    const float* Wq    = (const float*)d_in[3];
    const float* bq    = (const float*)d_in[4];
    const float* Wk    = (const float*)d_in[5];
    const float* bk    = (const float*)d_in[6];
    const float* Wv    = (const float*)d_in[7];
    const float* bv    = (const float*)d_in[8];
    const float* Wo    = (const float*)d_in[9];
    const float* bo    = (const float*)d_in[10];
    const float* gamma = (const float*)d_in[11];
    const float* beta  = (const float*)d_in[12];
    const float* demb  = (const float*)d_in[13];

    float* out = (float*)d_out;
    float* att = out + (size_t)BATCH * SEQ * DMODEL;

    const int M = BATCH * SEQ;   // 8192

    ln_kernel<<<M, 256>>>(features, gamma, beta);
    bins_kernel<<<(M + 255) / 256, 256>>>(boxes, image_sizes);

    dim3 gProj(DMODEL / 128, M / 128);   // (6, 64)
    gemm_nt128<1><<<gProj, 256>>>(Wq, bq, nullptr);
    gemm_nt128<2><<<gProj, 256>>>(Wk, bk, nullptr);
    gemm_nt128<3><<<gProj, 256>>>(Wv, bv, nullptr);

    attn_scores<<<dim3(SEQ / 64, SEQ / 64, BATCH * NHEAD), 256>>>(demb, att);
    softmax_rows<<<BATCH * NHEAD * SEQ, 128>>>(att);
    attn_pv<<<dim3(1, SEQ / 64, BATCH * NHEAD), 256>>>(att);

    gemm_nt128<0><<<gProj, 256>>>(Wo, bo, out);
}

// round 6
// speedup vs baseline: 1.2056x; 1.2056x over previous
#include <cuda_runtime.h>
#include <math.h>

#define BATCH  16
#define SEQ    512
#define DMODEL 768
#define NHEAD  12
#define DHEAD  64
#define NDIST  32

// ---------------- scratch (static device memory; referenced by symbol only) ----------------
__device__ float g_x  [BATCH*SEQ*DMODEL];
__device__ float g_q  [BATCH*SEQ*DMODEL];   // layout (B,H,N,DK)
__device__ float g_k  [BATCH*SEQ*DMODEL];   // layout (B,H,N,DK)
__device__ float g_v  [BATCH*SEQ*DMODEL];   // layout (B,H,N,DK)
__device__ float g_ctx[BATCH*SEQ*DMODEL];   // layout (B,N,H*DK)
__device__ int   g_px [BATCH*SEQ];
__device__ int   g_py [BATCH*SEQ];

// ---------------- LayerNorm: one block per token row, writes g_x ----------------
__global__ __launch_bounds__(256) void ln_kernel(
    const float* __restrict__ feat,
    const float* __restrict__ gamma,
    const float* __restrict__ beta)
{
    int row = blockIdx.x;
    const float* x = feat + (size_t)row * DMODEL;
    float* y = g_x + (size_t)row * DMODEL;
    int t = threadIdx.x;

    float v0 = x[t], v1 = x[t + 256], v2 = x[t + 512];
    float s  = v0 + v1 + v2;
    float q  = v0*v0 + v1*v1 + v2*v2;

    __shared__ float ss[8], sq[8];
    #pragma unroll
    for (int o = 16; o > 0; o >>= 1) {
        s += __shfl_xor_sync(0xffffffffu, s, o);
        q += __shfl_xor_sync(0xffffffffu, q, o);
    }
    if ((t & 31) == 0) { ss[t >> 5] = s; sq[t >> 5] = q; }
    __syncthreads();
    if (t == 0) {
        float a = 0.f, b2 = 0.f;
        #pragma unroll
        for (int i = 0; i < 8; i++) { a += ss[i]; b2 += sq[i]; }
        ss[0] = a; sq[0] = b2;
    }
    __syncthreads();
    float mean = ss[0] * (1.0f / DMODEL);
    float var  = sq[0] * (1.0f / DMODEL) - mean * mean;
    float inv  = rsqrtf(var + 1e-5f);

    y[t]       = (v0 - mean) * inv * gamma[t]       + beta[t];
    y[t + 256] = (v1 - mean) * inv * gamma[t + 256] + beta[t + 256];
    y[t + 512] = (v2 - mean) * inv * gamma[t + 512] + beta[t + 512];
}

// ---------------- patch bins (exact replica of reference semantics) ----------------
__global__ void bins_kernel(
    const float* __restrict__ boxes,
    const int* __restrict__ image_sizes)
{
    int idx = blockIdx.x * blockDim.x + threadIdx.x;
    if (idx >= BATCH * SEQ) return;
    int b = idx / SEQ;
    float w = (float)image_sizes[b * 4 + 0];
    float h = (float)image_sizes[b * 4 + 1];
    const float* bx = boxes + (size_t)idx * 4;
    float x0 = bx[0] * w, y0 = bx[1] * h, x1 = bx[2] * w, y1 = bx[3] * h;
    float spaw = floorf(w / 11.0f);
    float spah = floorf(h / 11.0f);
    float cx = floorf((x0 + x1) / 2.0f);
    float cy = floorf((y0 + y1) / 2.0f);
    int pxv = 0, pyv = 0;
    for (int j = 10; j >= 0; j--) {
        float lbw = (float)j * spaw, hbw = (float)(j + 1) * spaw;
        if (lbw <= cx && cx <= hbw) pxv = j;
        float lbh = (float)j * spah, hbh = (float)(j + 1) * spah;
        if (lbh <= cy && cy <= hbh) pyv = j;
    }
    g_px[idx] = pxv;
    g_py[idx] = pyv;
}

// ---------------- helpers for 3xTF32 tensor-core GEMM ----------------
__device__ __forceinline__ void cvt_hilo(float v, float& hi, float& lo)
{
    unsigned hu;
    asm("cvt.rna.tf32.f32 %0, %1;" : "=r"(hu) : "f"(v));
    float hf = __uint_as_float(hu);
    float lf = v - hf;
    unsigned lu;
    asm("cvt.rna.tf32.f32 %0, %1;" : "=r"(lu) : "f"(lf));
    hi = hf;
    lo = __uint_as_float(lu);
}

#define MMA_TF32(D, A, B)                                                        \
    asm volatile("mma.sync.aligned.m16n8k8.row.col.f32.tf32.tf32.f32 "           \
                 "{%0,%1,%2,%3},{%4,%5,%6,%7},{%8,%9},{%0,%1,%2,%3};"            \
                 : "+f"(D[0]), "+f"(D[1]), "+f"(D[2]), "+f"(D[3])                \
                 : "r"(A[0]), "r"(A[1]), "r"(A[2]), "r"(A[3]), "r"(B[0]), "r"(B[1]))

// ---------------- NT GEMM via tensor cores (3xTF32): C = A @ W^T + bias ----------------
// BM=BN=128, BK=16, 256 threads = 8 warps (warp_m in 0..3 -> 32 rows, warp_n in 0..1 -> 64 cols)
// smem layout [k][m^swz] with stride 136 and XOR swizzle: conflict-free fills and fragment loads.
// MODE 0: A=g_ctx, row-major out to Cout.  MODE 1/2/3: A=g_x, scatter to g_q/g_k/g_v (B,H,N,DK).
template<int MODE>
__global__ __launch_bounds__(256) void gemm_tf32(
    const float* __restrict__ W,
    const float* __restrict__ bias,
    float* __restrict__ Cout)
{
    const float* A = (MODE == 0) ? g_ctx : g_x;
    const int K = DMODEL;
    const int STR = 136;

    __shared__ float As_hi[16][136], As_lo[16][136];
    __shared__ float Ws_hi[16][136], Ws_lo[16][136];

    const int t    = threadIdx.x;
    const int lane = t & 31;
    const int wid  = t >> 5;
    const int warp_m = wid & 3;       // 0..3
    const int warp_n = wid >> 2;      // 0..1
    const int r = lane >> 2;          // 0..7
    const int c = lane & 3;           // 0..3

    const int row0 = blockIdx.y * 128;
    const int col0 = blockIdx.x * 128;

    // fill mapping: thread handles 2 float4 of A and 2 of W per iteration
    const int fm = t >> 2;            // 0..63  (rows fm and fm+64)
    const int kq = (t & 3) * 4;       // 0,4,8,12

    const float* Ap = A + (size_t)(row0 + fm) * K + kq;
    const float* Wp = W + (size_t)(col0 + fm) * K + kq;

    float d[2][8][4];
    #pragma unroll
    for (int i = 0; i < 2; i++)
        #pragma unroll
        for (int j = 0; j < 8; j++)
            #pragma unroll
            for (int e = 0; e < 4; e++) d[i][j][e] = 0.f;

    float4 aR0, aR1, wR0, wR1;
    aR0 = *(const float4*)(Ap);
    aR1 = *(const float4*)(Ap + (size_t)64 * K);
    wR0 = *(const float4*)(Wp);
    wR1 = *(const float4*)(Wp + (size_t)64 * K);

    const int NIT = K / 16;           // 48
    for (int it = 0; it < NIT; it++) {
        __syncthreads();
        // store hi/lo tiles (transposed [k][m], XOR swizzle on m by (k>>2)&3)
        {
            float va[4] = {aR0.x, aR0.y, aR0.z, aR0.w};
            float vb[4] = {aR1.x, aR1.y, aR1.z, aR1.w};
            float wa[4] = {wR0.x, wR0.y, wR0.z, wR0.w};
            float wb[4] = {wR1.x, wR1.y, wR1.z, wR1.w};
            #pragma unroll
            for (int j = 0; j < 4; j++) {
                int k = kq + j;
                int sw = ((k >> 2) & 3) << 3;
                float hi, lo;
                cvt_hilo(va[j], hi, lo);
                As_hi[k][fm ^ sw] = hi; As_lo[k][fm ^ sw] = lo;
                cvt_hilo(vb[j], hi, lo);
                As_hi[k][(fm + 64) ^ sw] = hi; As_lo[k][(fm + 64) ^ sw] = lo;
                cvt_hilo(wa[j], hi, lo);
                Ws_hi[k][fm ^ sw] = hi; Ws_lo[k][fm ^ sw] = lo;
                cvt_hilo(wb[j], hi, lo);
                Ws_hi[k][(fm + 64) ^ sw] = hi; Ws_lo[k][(fm + 64) ^ sw] = lo;
            }
        }
        __syncthreads();

        // prefetch next iteration's tiles
        if (it + 1 < NIT) {
            int k0 = (it + 1) * 16;
            aR0 = *(const float4*)(Ap + k0);
            aR1 = *(const float4*)(Ap + (size_t)64 * K + k0);
            wR0 = *(const float4*)(Wp + k0);
            wR1 = *(const float4*)(Wp + (size_t)64 * K + k0);
        }

        // two k8 steps
        #pragma unroll
        for (int k8o = 0; k8o < 16; k8o += 8) {
            int klo = k8o + c;        // k for a0/a1/b0
            int khi = k8o + c + 4;    // k for a2/a3/b1
            int swl = ((klo >> 2) & 3) << 3;
            int swh = ((khi >> 2) & 3) << 3;

            unsigned ah[2][4], al[2][4];
            #pragma unroll
            for (int mt = 0; mt < 2; mt++) {
                int rb = warp_m * 32 + mt * 16 + r;
                ah[mt][0] = __float_as_uint(As_hi[klo][(rb)     ^ swl]);
                ah[mt][1] = __float_as_uint(As_hi[klo][(rb + 8) ^ swl]);
                ah[mt][2] = __float_as_uint(As_hi[khi][(rb)     ^ swh]);
                ah[mt][3] = __float_as_uint(As_hi[khi][(rb + 8) ^ swh]);
                al[mt][0] = __float_as_uint(As_lo[klo][(rb)     ^ swl]);
                al[mt][1] = __float_as_uint(As_lo[klo][(rb + 8) ^ swl]);
                al[mt][2] = __float_as_uint(As_lo[khi][(rb)     ^ swh]);
                al[mt][3] = __float_as_uint(As_lo[khi][(rb + 8) ^ swh]);
            }
            unsigned bh[8][2], bl[8][2];
            #pragma unroll
            for (int nt = 0; nt < 8; nt++) {
                int nb = warp_n * 64 + nt * 8 + r;
                bh[nt][0] = __float_as_uint(Ws_hi[klo][nb ^ swl]);
                bh[nt][1] = __float_as_uint(Ws_hi[khi][nb ^ swh]);
                bl[nt][0] = __float_as_uint(Ws_lo[klo][nb ^ swl]);
                bl[nt][1] = __float_as_uint(Ws_lo[khi][nb ^ swh]);
            }
            #pragma unroll
            for (int mt = 0; mt < 2; mt++)
                #pragma unroll
                for (int nt = 0; nt < 8; nt++) {
                    MMA_TF32(d[mt][nt], ah[mt], bh[nt]);
                    MMA_TF32(d[mt][nt], ah[mt], bl[nt]);
                    MMA_TF32(d[mt][nt], al[mt], bh[nt]);
                }
        }
    }

    // epilogue
    float* Cdst = (MODE == 0) ? Cout : (MODE == 1) ? g_q : (MODE == 2) ? g_k : g_v;
    #pragma unroll
    for (int mt = 0; mt < 2; mt++) {
        int m0 = row0 + warp_m * 32 + mt * 16 + r;   // rows m0 and m0+8
        #pragma unroll
        for (int nt = 0; nt < 8; nt++) {
            int n = col0 + warp_n * 64 + nt * 8 + 2 * c;   // cols n, n+1 (n even)
            float b0v = bias[n], b1v = bias[n + 1];
            float v00 = d[mt][nt][0] + b0v, v01 = d[mt][nt][1] + b1v;
            float v10 = d[mt][nt][2] + b0v, v11 = d[mt][nt][3] + b1v;
            if (MODE == 0) {
                *(float2*)&Cdst[(size_t)m0 * DMODEL + n]       = make_float2(v00, v01);
                *(float2*)&Cdst[(size_t)(m0 + 8) * DMODEL + n] = make_float2(v10, v11);
            } else {
                int hh = n >> 6, dk = n & 63;                // n even -> dk, dk+1 same head
                int b1_ = m0 >> 9,       nq1 = m0 & 511;
                int b2_ = (m0 + 8) >> 9, nq2 = (m0 + 8) & 511;
                *(float2*)&Cdst[(((size_t)(b1_ * NHEAD + hh)) * SEQ + nq1) * DHEAD + dk] = make_float2(v00, v01);
                *(float2*)&Cdst[(((size_t)(b2_ * NHEAD + hh)) * SEQ + nq2) * DHEAD + dk] = make_float2(v10, v11);
            }
        }
    }
}

// ---------------- attention scores: S = QK^T/8 + dist_bias ----------------
__global__ __launch_bounds__(256) void attn_scores(
    const float* __restrict__ dist_emb, float* __restrict__ att)
{
    int bh = blockIdx.z;
    int b  = bh / NHEAD, h = bh % NHEAD;
    int q0 = blockIdx.y * 64, k0v = blockIdx.x * 64;

    __shared__ float Qs[64][68];
    __shared__ float Ks[64][68];
    __shared__ float emb[NDIST];
    __shared__ int   spx[2][64], spy[2][64];

    const float* Qb = g_q + (size_t)bh * SEQ * DHEAD;
    const float* Kb = g_k + (size_t)bh * SEQ * DHEAD;
    int t  = threadIdx.x;
    int lr = t >> 2;
    int lc = (t & 3) * 16;
    {
        const float* qp = Qb + (size_t)(q0 + lr) * DHEAD + lc;
        const float* kp = Kb + (size_t)(k0v + lr) * DHEAD + lc;
        #pragma unroll
        for (int u = 0; u < 4; u++) {
            float4 v = *(const float4*)(qp + u * 4);
            Qs[lc + u*4 + 0][lr] = v.x; Qs[lc + u*4 + 1][lr] = v.y;
            Qs[lc + u*4 + 2][lr] = v.z; Qs[lc + u*4 + 3][lr] = v.w;
            float4 w = *(const float4*)(kp + u * 4);
            Ks[lc + u*4 + 0][lr] = w.x; Ks[lc + u*4 + 1][lr] = w.y;
            Ks[lc + u*4 + 2][lr] = w.z; Ks[lc + u*4 + 3][lr] = w.w;
        }
    }
    if (t < NDIST) emb[t] = dist_emb[t * NHEAD + h];
    if (t < 64) {
        spx[0][t] = g_px[b * SEQ + q0 + t];
        spy[0][t] = g_py[b * SEQ + q0 + t];
    } else if (t < 128) {
        int u = t - 64;
        spx[1][u] = g_px[b * SEQ + k0v + u];
        spy[1][u] = g_py[b * SEQ + k0v + u];
    }
    __syncthreads();

    int tx = t & 15, ty = t >> 4;
    float acc[4][4];
    #pragma unroll
    for (int i = 0; i < 4; i++)
        #pragma unroll
        for (int j = 0; j < 4; j++) acc[i][j] = 0.f;

    #pragma unroll 8
    for (int kk = 0; kk < 64; kk++) {
        float4 av = *(const float4*)&Qs[kk][ty * 4];
        float4 bv = *(const float4*)&Ks[kk][tx * 4];
        float a[4]  = {av.x, av.y, av.z, av.w};
        float bb[4] = {bv.x, bv.y, bv.z, bv.w};
        #pragma unroll
        for (int i = 0; i < 4; i++)
            #pragma unroll
            for (int j = 0; j < 4; j++)
                acc[i][j] = fmaf(a[i], bb[j], acc[i][j]);
    }

    float* outp = att + ((size_t)bh * SEQ + q0) * SEQ + k0v;
    #pragma unroll
    for (int i = 0; i < 4; i++) {
        int qi = ty * 4 + i;
        #pragma unroll
        for (int j = 0; j < 4; j++) {
            int kj = tx * 4 + j;
            int dx = spx[1][kj] - spx[0][qi];
            int dy = spy[1][kj] - spy[0][qi];
            int bin = (int)(sqrtf((float)(dx * dx + dy * dy)) * 2.0f);
            outp[(size_t)qi * SEQ + kj] = acc[i][j] * 0.125f + emb[bin];
        }
    }
}

// ---------------- row softmax over 512 keys (in place) ----------------
__global__ __launch_bounds__(128) void softmax_rows(float* __restrict__ att)
{
    size_t row = blockIdx.x;
    float* p = att + row * SEQ;
    int t = threadIdx.x;
    float4 v = ((float4*)p)[t];

    __shared__ float red[4];
    float m = fmaxf(fmaxf(v.x, v.y), fmaxf(v.z, v.w));
    #pragma unroll
    for (int o = 16; o > 0; o >>= 1) m = fmaxf(m, __shfl_xor_sync(0xffffffffu, m, o));
    if ((t & 31) == 0) red[t >> 5] = m;
    __syncthreads();
    m = fmaxf(fmaxf(red[0], red[1]), fmaxf(red[2], red[3]));
    __syncthreads();

    float e0 = expf(v.x - m), e1 = expf(v.y - m), e2 = expf(v.z - m), e3 = expf(v.w - m);
    float s = e0 + e1 + e2 + e3;
    #pragma unroll
    for (int o = 16; o > 0; o >>= 1) s += __shfl_xor_sync(0xffffffffu, s, o);
    if ((t & 31) == 0) red[t >> 5] = s;
    __syncthreads();
    s = red[0] + red[1] + red[2] + red[3];
    float inv = 1.0f / s;

    float4 r = make_float4(e0 * inv, e1 * inv, e2 * inv, e3 * inv);
    ((float4*)p)[t] = r;
}

// ---------------- PV: g_ctx = att @ V ----------------
__global__ __launch_bounds__(256) void attn_pv(const float* __restrict__ att)
{
    int bh = blockIdx.z;
    int b  = bh / NHEAD, h = bh % NHEAD;
    int q0 = blockIdx.y * 64;

    __shared__ float Ps[32][68];
    __shared__ float Vs[32][68];
    const float* Pb = att + ((size_t)bh * SEQ + q0) * SEQ;
    const float* Vb = g_v + (size_t)bh * SEQ * DHEAD;

    int t  = threadIdx.x;
    int tx = t & 15, ty = t >> 4;
    int pr = t >> 2, pc = (t & 3) * 8;
    int vr = t >> 3, vc = (t & 7) * 8;

    float acc[4][4];
    #pragma unroll
    for (int i = 0; i < 4; i++)
        #pragma unroll
        for (int j = 0; j < 4; j++) acc[i][j] = 0.f;

    for (int k0 = 0; k0 < SEQ; k0 += 32) {
        float4 p0 = *(const float4*)(Pb + (size_t)pr * SEQ + k0 + pc);
        float4 p1 = *(const float4*)(Pb + (size_t)pr * SEQ + k0 + pc + 4);
        float4 v0 = *(const float4*)(Vb + (size_t)(k0 + vr) * DHEAD + vc);
        float4 v1 = *(const float4*)(Vb + (size_t)(k0 + vr) * DHEAD + vc + 4);
        __syncthreads();
        Ps[pc + 0][pr] = p0.x; Ps[pc + 1][pr] = p0.y; Ps[pc + 2][pr] = p0.z; Ps[pc + 3][pr] = p0.w;
        Ps[pc + 4][pr] = p1.x; Ps[pc + 5][pr] = p1.y; Ps[pc + 6][pr] = p1.z; Ps[pc + 7][pr] = p1.w;
        Vs[vr][vc + 0] = v0.x; Vs[vr][vc + 1] = v0.y; Vs[vr][vc + 2] = v0.z; Vs[vr][vc + 3] = v0.w;
        Vs[vr][vc + 4] = v1.x; Vs[vr][vc + 5] = v1.y; Vs[vr][vc + 6] = v1.z; Vs[vr][vc + 7] = v1.w;
        __syncthreads();
        #pragma unroll 8
        for (int kk = 0; kk < 32; kk++) {
            float4 av = *(const float4*)&Ps[kk][ty * 4];
            float4 bv = *(const float4*)&Vs[kk][tx * 4];
            float a[4]  = {av.x, av.y, av.z, av.w};
            float bb[4] = {bv.x, bv.y, bv.z, bv.w};
            #pragma unroll
            for (int i = 0; i < 4; i++)
                #pragma unroll
                for (int j = 0; j < 4; j++)
                    acc[i][j] = fmaf(a[i], bb[j], acc[i][j]);
        }
    }

    #pragma unroll
    for (int i = 0; i < 4; i++) {
        int q = q0 + ty * 4 + i;
        #pragma unroll
        for (int j = 0; j < 4; j++) {
            int d = tx * 4 + j;
            g_ctx[((size_t)(b * SEQ + q)) * DMODEL + h * DHEAD + d] = acc[i][j];
        }
    }
}

// ---------------- launch: pure kernel launches, no other runtime API ----------------
extern "C" void kernel_launch(void* const* d_in, const int* in_sizes, int n_in,
                              void* d_out, int out_size)
{
    const float* features    = (const float*)d_in[0];
    const float* boxes       = (const float*)d_in[1];
    const int*   image_sizes = (const int*)  d_in[2];
    const float* Wq    = (const float*)d_in[3];
    const float* bq    = (const float*)d_in[4];
    const float* Wk    = (const float*)d_in[5];
    const float* bk    = (const float*)d_in[6];
    const float* Wv    = (const float*)d_in[7];
    const float* bv    = (const float*)d_in[8];
    const float* Wo    = (const float*)d_in[9];
    const float* bo    = (const float*)d_in[10];
    const float* gamma = (const float*)d_in[11];
    const float* beta  = (const float*)d_in[12];
    const float* demb  = (const float*)d_in[13];

    float* out = (float*)d_out;
    float* att = out + (size_t)BATCH * SEQ * DMODEL;

    const int M = BATCH * SEQ;   // 8192

    ln_kernel<<<M, 256>>>(features, gamma, beta);
    bins_kernel<<<(M + 255) / 256, 256>>>(boxes, image_sizes);

    dim3 gProj(DMODEL / 128, M / 128);   // (6, 64)
    gemm_tf32<1><<<gProj, 256>>>(Wq, bq, nullptr);
    gemm_tf32<2><<<gProj, 256>>>(Wk, bk, nullptr);
    gemm_tf32<3><<<gProj, 256>>>(Wv, bv, nullptr);

    attn_scores<<<dim3(SEQ / 64, SEQ / 64, BATCH * NHEAD), 256>>>(demb, att);
    softmax_rows<<<BATCH * NHEAD * SEQ, 128>>>(att);
    attn_pv<<<dim3(1, SEQ / 64, BATCH * NHEAD), 256>>>(att);

    gemm_tf32<0><<<gProj, 256>>>(Wo, bo, out);
}

// round 8
// speedup vs baseline: 1.7720x; 1.4698x over previous
#include <cuda_runtime.h>
#include <cuda_bf16.h>
#include <math.h>

#define BATCH  16
#define SEQ    512
#define DMODEL 768
#define NHEAD  12
#define DHEAD  64
#define NDIST  32

// ---------------- scratch (static device memory; referenced by symbol only) ----------------
__device__ float g_x  [BATCH*SEQ*DMODEL];
__device__ float g_q  [BATCH*SEQ*DMODEL];   // layout (B,H,N,DK)
__device__ float g_k  [BATCH*SEQ*DMODEL];   // layout (B,H,N,DK)
__device__ float g_v  [BATCH*SEQ*DMODEL];   // layout (B,H,N,DK)
__device__ float g_ctx[BATCH*SEQ*DMODEL];   // layout (B,N,H*DK)
__device__ int   g_px [BATCH*SEQ];
__device__ int   g_py [BATCH*SEQ];

// ---------------- LayerNorm: one block per token row, writes g_x ----------------
__global__ __launch_bounds__(256) void ln_kernel(
    const float* __restrict__ feat,
    const float* __restrict__ gamma,
    const float* __restrict__ beta)
{
    int row = blockIdx.x;
    const float* x = feat + (size_t)row * DMODEL;
    float* y = g_x + (size_t)row * DMODEL;
    int t = threadIdx.x;

    float v0 = x[t], v1 = x[t + 256], v2 = x[t + 512];
    float s  = v0 + v1 + v2;
    float q  = v0*v0 + v1*v1 + v2*v2;

    __shared__ float ss[8], sq[8];
    #pragma unroll
    for (int o = 16; o > 0; o >>= 1) {
        s += __shfl_xor_sync(0xffffffffu, s, o);
        q += __shfl_xor_sync(0xffffffffu, q, o);
    }
    if ((t & 31) == 0) { ss[t >> 5] = s; sq[t >> 5] = q; }
    __syncthreads();
    if (t == 0) {
        float a = 0.f, b2 = 0.f;
        #pragma unroll
        for (int i = 0; i < 8; i++) { a += ss[i]; b2 += sq[i]; }
        ss[0] = a; sq[0] = b2;
    }
    __syncthreads();
    float mean = ss[0] * (1.0f / DMODEL);
    float var  = sq[0] * (1.0f / DMODEL) - mean * mean;
    float inv  = rsqrtf(var + 1e-5f);

    y[t]       = (v0 - mean) * inv * gamma[t]       + beta[t];
    y[t + 256] = (v1 - mean) * inv * gamma[t + 256] + beta[t + 256];
    y[t + 512] = (v2 - mean) * inv * gamma[t + 512] + beta[t + 512];
}

// ---------------- patch bins (exact replica of reference semantics) ----------------
__global__ void bins_kernel(
    const float* __restrict__ boxes,
    const int* __restrict__ image_sizes)
{
    int idx = blockIdx.x * blockDim.x + threadIdx.x;
    if (idx >= BATCH * SEQ) return;
    int b = idx / SEQ;
    float w = (float)image_sizes[b * 4 + 0];
    float h = (float)image_sizes[b * 4 + 1];
    const float* bx = boxes + (size_t)idx * 4;
    float x0 = bx[0] * w, y0 = bx[1] * h, x1 = bx[2] * w, y1 = bx[3] * h;
    float spaw = floorf(w / 11.0f);
    float spah = floorf(h / 11.0f);
    float cx = floorf((x0 + x1) / 2.0f);
    float cy = floorf((y0 + y1) / 2.0f);
    int pxv = 0, pyv = 0;
    for (int j = 10; j >= 0; j--) {
        float lbw = (float)j * spaw, hbw = (float)(j + 1) * spaw;
        if (lbw <= cx && cx <= hbw) pxv = j;
        float lbh = (float)j * spah, hbh = (float)(j + 1) * spah;
        if (lbh <= cy && cy <= hbh) pyv = j;
    }
    g_px[idx] = pxv;
    g_py[idx] = pyv;
}

// ---------------- helpers for 3xBF16 tensor-core GEMM ----------------
__device__ __forceinline__ void bf16_split(float v, __nv_bfloat16& h, __nv_bfloat16& l)
{
    h = __float2bfloat16_rn(v);
    l = __float2bfloat16_rn(v - __bfloat162float(h));
}

__device__ __forceinline__ unsigned bf16pack(__nv_bfloat16 a, __nv_bfloat16 b)
{
    __nv_bfloat162 p = __halves2bfloat162(a, b);   // .x (low) = a = even-k
    return *reinterpret_cast<unsigned*>(&p);
}

// store one float4 (4 consecutive k) of one row into hi/lo kpair planes
__device__ __forceinline__ void store_row_bf16(
    unsigned (*Hi)[136], unsigned (*Lo)[136], int kp0, int m, float4 v)
{
    __nv_bfloat16 h0,l0,h1,l1,h2,l2,h3,l3;
    bf16_split(v.x, h0, l0); bf16_split(v.y, h1, l1);
    bf16_split(v.z, h2, l2); bf16_split(v.w, h3, l3);
    Hi[kp0    ][m] = bf16pack(h0, h1);
    Hi[kp0 + 1][m] = bf16pack(h2, h3);
    Lo[kp0    ][m] = bf16pack(l0, l1);
    Lo[kp0 + 1][m] = bf16pack(l2, l3);
}

#define MMA_BF16(D, A, B0, B1)                                                   \
    asm volatile("mma.sync.aligned.m16n8k16.row.col.f32.bf16.bf16.f32 "          \
                 "{%0,%1,%2,%3},{%4,%5,%6,%7},{%8,%9},{%0,%1,%2,%3};"            \
                 : "+f"(D[0]), "+f"(D[1]), "+f"(D[2]), "+f"(D[3])                \
                 : "r"(A[0]), "r"(A[1]), "r"(A[2]), "r"(A[3]), "r"(B0), "r"(B1))

// ---------------- NT GEMM via tensor cores (3xBF16): C = A @ W^T + bias ----------------
// BM=BN=128, BK=16, 256 threads = 8 warps (warp_m 0..3 -> 32 rows, warp_n 0..1 -> 64 cols).
// smem: double-buffered [kpair][m] uint32 planes (bf16x2 along k), stride 136 -> conflict-free
// fragment loads (banks 8*kpair + r are all distinct for kpair 0..3, r 0..7).
// MODE 0: A=g_ctx, row-major out to Cout.  MODE 1/2/3: A=g_x, scatter to g_q/g_k/g_v.
template<int MODE>
__global__ __launch_bounds__(256) void gemm_bf16x3(
    const float* __restrict__ W,
    const float* __restrict__ bias,
    float* __restrict__ Cout)
{
    const float* A = (MODE == 0) ? g_ctx : g_x;
    const int K = DMODEL;

    __shared__ unsigned As_hi[2][8][136], As_lo[2][8][136];
    __shared__ unsigned Ws_hi[2][8][136], Ws_lo[2][8][136];

    const int t    = threadIdx.x;
    const int lane = t & 31;
    const int wid  = t >> 5;
    const int warp_m = wid & 3;       // 0..3
    const int warp_n = wid >> 2;      // 0..1
    const int r = lane >> 2;          // 0..7
    const int c = lane & 3;           // 0..3

    const int row0 = blockIdx.y * 128;
    const int col0 = blockIdx.x * 128;

    // fill mapping: thread covers rows fm, fm+64 of A and W, k-quad kq..kq+3
    const int fm = t >> 2;            // 0..63
    const int kq = (t & 3) * 4;       // 0,4,8,12
    const int kp0 = (t & 3) * 2;      // kpair index of kq

    const float* Ap = A + (size_t)(row0 + fm) * K + kq;
    const float* Wp = W + (size_t)(col0 + fm) * K + kq;

    float d[2][8][4];
    #pragma unroll
    for (int i = 0; i < 2; i++)
        #pragma unroll
        for (int j = 0; j < 8; j++)
            #pragma unroll
            for (int e = 0; e < 4; e++) d[i][j][e] = 0.f;

    float4 aR0 = *(const float4*)(Ap);
    float4 aR1 = *(const float4*)(Ap + (size_t)64 * K);
    float4 wR0 = *(const float4*)(Wp);
    float4 wR1 = *(const float4*)(Wp + (size_t)64 * K);

    // store stage 0
    store_row_bf16(As_hi[0], As_lo[0], kp0, fm,      aR0);
    store_row_bf16(As_hi[0], As_lo[0], kp0, fm + 64, aR1);
    store_row_bf16(Ws_hi[0], Ws_lo[0], kp0, fm,      wR0);
    store_row_bf16(Ws_hi[0], Ws_lo[0], kp0, fm + 64, wR1);
    __syncthreads();

    const int NIT = K / 16;           // 48
    for (int it = 0; it < NIT; it++) {
        const int buf = it & 1;
        if (it + 1 < NIT) {
            int k0 = (it + 1) * 16;
            aR0 = *(const float4*)(Ap + k0);
            aR1 = *(const float4*)(Ap + (size_t)64 * K + k0);
            wR0 = *(const float4*)(Wp + k0);
            wR1 = *(const float4*)(Wp + (size_t)64 * K + k0);
        }

        // compute on buf
        {
            unsigned (*Ah)[136] = As_hi[buf];
            unsigned (*Al)[136] = As_lo[buf];
            unsigned (*Wh)[136] = Ws_hi[buf];
            unsigned (*Wl)[136] = Ws_lo[buf];

            unsigned ah[2][4], al[2][4];
            #pragma unroll
            for (int mt = 0; mt < 2; mt++) {
                int rb = warp_m * 32 + mt * 16 + r;
                ah[mt][0] = Ah[c][rb];     ah[mt][1] = Ah[c][rb + 8];
                ah[mt][2] = Ah[c + 4][rb]; ah[mt][3] = Ah[c + 4][rb + 8];
                al[mt][0] = Al[c][rb];     al[mt][1] = Al[c][rb + 8];
                al[mt][2] = Al[c + 4][rb]; al[mt][3] = Al[c + 4][rb + 8];
            }
            #pragma unroll
            for (int nt = 0; nt < 8; nt++) {
                int nb = warp_n * 64 + nt * 8 + r;
                unsigned b0h = Wh[c][nb], b1h = Wh[c + 4][nb];
                unsigned b0l = Wl[c][nb], b1l = Wl[c + 4][nb];
                #pragma unroll
                for (int mt = 0; mt < 2; mt++) {
                    MMA_BF16(d[mt][nt], ah[mt], b0h, b1h);
                    MMA_BF16(d[mt][nt], ah[mt], b0l, b1l);
                    MMA_BF16(d[mt][nt], al[mt], b0h, b1h);
                }
            }
        }

        if (it + 1 < NIT) {
            int nb = buf ^ 1;
            store_row_bf16(As_hi[nb], As_lo[nb], kp0, fm,      aR0);
            store_row_bf16(As_hi[nb], As_lo[nb], kp0, fm + 64, aR1);
            store_row_bf16(Ws_hi[nb], Ws_lo[nb], kp0, fm,      wR0);
            store_row_bf16(Ws_hi[nb], Ws_lo[nb], kp0, fm + 64, wR1);
        }
        __syncthreads();
    }

    // epilogue (same fragment layout as m16n8 tf32 version)
    float* Cdst = (MODE == 0) ? Cout : (MODE == 1) ? g_q : (MODE == 2) ? g_k : g_v;
    #pragma unroll
    for (int mt = 0; mt < 2; mt++) {
        int m0 = row0 + warp_m * 32 + mt * 16 + r;   // rows m0 and m0+8
        #pragma unroll
        for (int nt = 0; nt < 8; nt++) {
            int n = col0 + warp_n * 64 + nt * 8 + 2 * c;   // cols n, n+1 (n even)
            float b0v = bias[n], b1v = bias[n + 1];
            float v00 = d[mt][nt][0] + b0v, v01 = d[mt][nt][1] + b1v;
            float v10 = d[mt][nt][2] + b0v, v11 = d[mt][nt][3] + b1v;
            if (MODE == 0) {
                *(float2*)&Cdst[(size_t)m0 * DMODEL + n]       = make_float2(v00, v01);
                *(float2*)&Cdst[(size_t)(m0 + 8) * DMODEL + n] = make_float2(v10, v11);
            } else {
                int hh = n >> 6, dk = n & 63;                // n even -> dk, dk+1 same head
                int b1_ = m0 >> 9,       nq1 = m0 & 511;
                int b2_ = (m0 + 8) >> 9, nq2 = (m0 + 8) & 511;
                *(float2*)&Cdst[(((size_t)(b1_ * NHEAD + hh)) * SEQ + nq1) * DHEAD + dk] = make_float2(v00, v01);
                *(float2*)&Cdst[(((size_t)(b2_ * NHEAD + hh)) * SEQ + nq2) * DHEAD + dk] = make_float2(v10, v11);
            }
        }
    }
}

// ---------------- attention scores: S = QK^T/8 + dist_bias ----------------
__global__ __launch_bounds__(256) void attn_scores(
    const float* __restrict__ dist_emb, float* __restrict__ att)
{
    int bh = blockIdx.z;
    int b  = bh / NHEAD, h = bh % NHEAD;
    int q0 = blockIdx.y * 64, k0v = blockIdx.x * 64;

    __shared__ float Qs[64][68];
    __shared__ float Ks[64][68];
    __shared__ float emb[NDIST];
    __shared__ int   spx[2][64], spy[2][64];

    const float* Qb = g_q + (size_t)bh * SEQ * DHEAD;
    const float* Kb = g_k + (size_t)bh * SEQ * DHEAD;
    int t  = threadIdx.x;
    int lr = t >> 2;
    int lc = (t & 3) * 16;
    {
        const float* qp = Qb + (size_t)(q0 + lr) * DHEAD + lc;
        const float* kp = Kb + (size_t)(k0v + lr) * DHEAD + lc;
        #pragma unroll
        for (int u = 0; u < 4; u++) {
            float4 v = *(const float4*)(qp + u * 4);
            Qs[lc + u*4 + 0][lr] = v.x; Qs[lc + u*4 + 1][lr] = v.y;
            Qs[lc + u*4 + 2][lr] = v.z; Qs[lc + u*4 + 3][lr] = v.w;
            float4 w = *(const float4*)(kp + u * 4);
            Ks[lc + u*4 + 0][lr] = w.x; Ks[lc + u*4 + 1][lr] = w.y;
            Ks[lc + u*4 + 2][lr] = w.z; Ks[lc + u*4 + 3][lr] = w.w;
        }
    }
    if (t < NDIST) emb[t] = dist_emb[t * NHEAD + h];
    if (t < 64) {
        spx[0][t] = g_px[b * SEQ + q0 + t];
        spy[0][t] = g_py[b * SEQ + q0 + t];
    } else if (t < 128) {
        int u = t - 64;
        spx[1][u] = g_px[b * SEQ + k0v + u];
        spy[1][u] = g_py[b * SEQ + k0v + u];
    }
    __syncthreads();

    int tx = t & 15, ty = t >> 4;
    float acc[4][4];
    #pragma unroll
    for (int i = 0; i < 4; i++)
        #pragma unroll
        for (int j = 0; j < 4; j++) acc[i][j] = 0.f;

    #pragma unroll 8
    for (int kk = 0; kk < 64; kk++) {
        float4 av = *(const float4*)&Qs[kk][ty * 4];
        float4 bv = *(const float4*)&Ks[kk][tx * 4];
        float a[4]  = {av.x, av.y, av.z, av.w};
        float bb[4] = {bv.x, bv.y, bv.z, bv.w};
        #pragma unroll
        for (int i = 0; i < 4; i++)
            #pragma unroll
            for (int j = 0; j < 4; j++)
                acc[i][j] = fmaf(a[i], bb[j], acc[i][j]);
    }

    float* outp = att + ((size_t)bh * SEQ + q0) * SEQ + k0v;
    #pragma unroll
    for (int i = 0; i < 4; i++) {
        int qi = ty * 4 + i;
        #pragma unroll
        for (int j = 0; j < 4; j++) {
            int kj = tx * 4 + j;
            int dx = spx[1][kj] - spx[0][qi];
            int dy = spy[1][kj] - spy[0][qi];
            int bin = (int)(sqrtf((float)(dx * dx + dy * dy)) * 2.0f);
            outp[(size_t)qi * SEQ + kj] = acc[i][j] * 0.125f + emb[bin];
        }
    }
}

// ---------------- row softmax over 512 keys (in place) ----------------
__global__ __launch_bounds__(128) void softmax_rows(float* __restrict__ att)
{
    size_t row = blockIdx.x;
    float* p = att + row * SEQ;
    int t = threadIdx.x;
    float4 v = ((float4*)p)[t];

    __shared__ float red[4];
    float m = fmaxf(fmaxf(v.x, v.y), fmaxf(v.z, v.w));
    #pragma unroll
    for (int o = 16; o > 0; o >>= 1) m = fmaxf(m, __shfl_xor_sync(0xffffffffu, m, o));
    if ((t & 31) == 0) red[t >> 5] = m;
    __syncthreads();
    m = fmaxf(fmaxf(red[0], red[1]), fmaxf(red[2], red[3]));
    __syncthreads();

    float e0 = expf(v.x - m), e1 = expf(v.y - m), e2 = expf(v.z - m), e3 = expf(v.w - m);
    float s = e0 + e1 + e2 + e3;
    #pragma unroll
    for (int o = 16; o > 0; o >>= 1) s += __shfl_xor_sync(0xffffffffu, s, o);
    if ((t & 31) == 0) red[t >> 5] = s;
    __syncthreads();
    s = red[0] + red[1] + red[2] + red[3];
    float inv = 1.0f / s;

    float4 r = make_float4(e0 * inv, e1 * inv, e2 * inv, e3 * inv);
    ((float4*)p)[t] = r;
}

// ---------------- PV: g_ctx = att @ V ----------------
__global__ __launch_bounds__(256) void attn_pv(const float* __restrict__ att)
{
    int bh = blockIdx.z;
    int b  = bh / NHEAD, h = bh % NHEAD;
    int q0 = blockIdx.y * 64;

    __shared__ float Ps[32][68];
    __shared__ float Vs[32][68];
    const float* Pb = att + ((size_t)bh * SEQ + q0) * SEQ;
    const float* Vb = g_v + (size_t)bh * SEQ * DHEAD;

    int t  = threadIdx.x;
    int tx = t & 15, ty = t >> 4;
    int pr = t >> 2, pc = (t & 3) * 8;
    int vr = t >> 3, vc = (t & 7) * 8;

    float acc[4][4];
    #pragma unroll
    for (int i = 0; i < 4; i++)
        #pragma unroll
        for (int j = 0; j < 4; j++) acc[i][j] = 0.f;

    for (int k0 = 0; k0 < SEQ; k0 += 32) {
        float4 p0 = *(const float4*)(Pb + (size_t)pr * SEQ + k0 + pc);
        float4 p1 = *(const float4*)(Pb + (size_t)pr * SEQ + k0 + pc + 4);
        float4 v0 = *(const float4*)(Vb + (size_t)(k0 + vr) * DHEAD + vc);
        float4 v1 = *(const float4*)(Vb + (size_t)(k0 + vr) * DHEAD + vc + 4);
        __syncthreads();
        Ps[pc + 0][pr] = p0.x; Ps[pc + 1][pr] = p0.y; Ps[pc + 2][pr] = p0.z; Ps[pc + 3][pr] = p0.w;
        Ps[pc + 4][pr] = p1.x; Ps[pc + 5][pr] = p1.y; Ps[pc + 6][pr] = p1.z; Ps[pc + 7][pr] = p1.w;
        Vs[vr][vc + 0] = v0.x; Vs[vr][vc + 1] = v0.y; Vs[vr][vc + 2] = v0.z; Vs[vr][vc + 3] = v0.w;
        Vs[vr][vc + 4] = v1.x; Vs[vr][vc + 5] = v1.y; Vs[vr][vc + 6] = v1.z; Vs[vr][vc + 7] = v1.w;
        __syncthreads();
        #pragma unroll 8
        for (int kk = 0; kk < 32; kk++) {
            float4 av = *(const float4*)&Ps[kk][ty * 4];
            float4 bv = *(const float4*)&Vs[kk][tx * 4];
            float a[4]  = {av.x, av.y, av.z, av.w};
            float bb[4] = {bv.x, bv.y, bv.z, bv.w};
            #pragma unroll
            for (int i = 0; i < 4; i++)
                #pragma unroll
                for (int j = 0; j < 4; j++)
                    acc[i][j] = fmaf(a[i], bb[j], acc[i][j]);
        }
    }

    #pragma unroll
    for (int i = 0; i < 4; i++) {
        int q = q0 + ty * 4 + i;
        #pragma unroll
        for (int j = 0; j < 4; j++) {
            int d = tx * 4 + j;
            g_ctx[((size_t)(b * SEQ + q)) * DMODEL + h * DHEAD + d] = acc[i][j];
        }
    }
}

// ---------------- launch: pure kernel launches, no other runtime API ----------------
extern "C" void kernel_launch(void* const* d_in, const int* in_sizes, int n_in,
                              void* d_out, int out_size)
{
    const float* features    = (const float*)d_in[0];
    const float* boxes       = (const float*)d_in[1];
    const int*   image_sizes = (const int*)  d_in[2];
    const float* Wq    = (const float*)d_in[3];
    const float* bq    = (const float*)d_in[4];
    const float* Wk    = (const float*)d_in[5];
    const float* bk    = (const float*)d_in[6];
    const float* Wv    = (const float*)d_in[7];
    const float* bv    = (const float*)d_in[8];
    const float* Wo    = (const float*)d_in[9];
    const float* bo    = (const float*)d_in[10];
    const float* gamma = (const float*)d_in[11];
    const float* beta  = (const float*)d_in[12];
    const float* demb  = (const float*)d_in[13];

    float* out = (float*)d_out;
    float* att = out + (size_t)BATCH * SEQ * DMODEL;

    const int M = BATCH * SEQ;   // 8192

    ln_kernel<<<M, 256>>>(features, gamma, beta);
    bins_kernel<<<(M + 255) / 256, 256>>>(boxes, image_sizes);

    dim3 gProj(DMODEL / 128, M / 128);   // (6, 64)
    gemm_bf16x3<1><<<gProj, 256>>>(Wq, bq, nullptr);
    gemm_bf16x3<2><<<gProj, 256>>>(Wk, bk, nullptr);
    gemm_bf16x3<3><<<gProj, 256>>>(Wv, bv, nullptr);

    attn_scores<<<dim3(SEQ / 64, SEQ / 64, BATCH * NHEAD), 256>>>(demb, att);
    softmax_rows<<<BATCH * NHEAD * SEQ, 128>>>(att);
    attn_pv<<<dim3(1, SEQ / 64, BATCH * NHEAD), 256>>>(att);

    gemm_bf16x3<0><<<gProj, 256>>>(Wo, bo, out);
}

// round 9
// speedup vs baseline: 1.9390x; 1.0942x over previous
#include <cuda_runtime.h>
#include <cuda_bf16.h>
#include <math.h>

#define BATCH  16
#define SEQ    512
#define DMODEL 768
#define NHEAD  12
#define DHEAD  64
#define NDIST  32

// ---------------- scratch (static device memory; referenced by symbol only) ----------------
__device__ float g_x  [BATCH*SEQ*DMODEL];
__device__ float g_q  [BATCH*SEQ*DMODEL];   // layout (B,H,N,DK)
__device__ float g_k  [BATCH*SEQ*DMODEL];   // layout (B,H,N,DK)
__device__ float g_v  [BATCH*SEQ*DMODEL];   // layout (B,H,N,DK)
__device__ float g_ctx[BATCH*SEQ*DMODEL];   // layout (B,N,H*DK)
__device__ int   g_px [BATCH*SEQ];
__device__ int   g_py [BATCH*SEQ];

// ---------------- LayerNorm ----------------
__global__ __launch_bounds__(256) void ln_kernel(
    const float* __restrict__ feat,
    const float* __restrict__ gamma,
    const float* __restrict__ beta)
{
    int row = blockIdx.x;
    const float* x = feat + (size_t)row * DMODEL;
    float* y = g_x + (size_t)row * DMODEL;
    int t = threadIdx.x;

    float v0 = x[t], v1 = x[t + 256], v2 = x[t + 512];
    float s  = v0 + v1 + v2;
    float q  = v0*v0 + v1*v1 + v2*v2;

    __shared__ float ss[8], sq[8];
    #pragma unroll
    for (int o = 16; o > 0; o >>= 1) {
        s += __shfl_xor_sync(0xffffffffu, s, o);
        q += __shfl_xor_sync(0xffffffffu, q, o);
    }
    if ((t & 31) == 0) { ss[t >> 5] = s; sq[t >> 5] = q; }
    __syncthreads();
    if (t == 0) {
        float a = 0.f, b2 = 0.f;
        #pragma unroll
        for (int i = 0; i < 8; i++) { a += ss[i]; b2 += sq[i]; }
        ss[0] = a; sq[0] = b2;
    }
    __syncthreads();
    float mean = ss[0] * (1.0f / DMODEL);
    float var  = sq[0] * (1.0f / DMODEL) - mean * mean;
    float inv  = rsqrtf(var + 1e-5f);

    y[t]       = (v0 - mean) * inv * gamma[t]       + beta[t];
    y[t + 256] = (v1 - mean) * inv * gamma[t + 256] + beta[t + 256];
    y[t + 512] = (v2 - mean) * inv * gamma[t + 512] + beta[t + 512];
}

// ---------------- patch bins (exact replica of reference semantics) ----------------
__global__ void bins_kernel(
    const float* __restrict__ boxes,
    const int* __restrict__ image_sizes)
{
    int idx = blockIdx.x * blockDim.x + threadIdx.x;
    if (idx >= BATCH * SEQ) return;
    int b = idx / SEQ;
    float w = (float)image_sizes[b * 4 + 0];
    float h = (float)image_sizes[b * 4 + 1];
    const float* bx = boxes + (size_t)idx * 4;
    float x0 = bx[0] * w, y0 = bx[1] * h, x1 = bx[2] * w, y1 = bx[3] * h;
    float spaw = floorf(w / 11.0f);
    float spah = floorf(h / 11.0f);
    float cx = floorf((x0 + x1) / 2.0f);
    float cy = floorf((y0 + y1) / 2.0f);
    int pxv = 0, pyv = 0;
    for (int j = 10; j >= 0; j--) {
        float lbw = (float)j * spaw, hbw = (float)(j + 1) * spaw;
        if (lbw <= cx && cx <= hbw) pxv = j;
        float lbh = (float)j * spah, hbh = (float)(j + 1) * spah;
        if (lbh <= cy && cy <= hbh) pyv = j;
    }
    g_px[idx] = pxv;
    g_py[idx] = pyv;
}

// ---------------- bf16 3x helpers ----------------
__device__ __forceinline__ void bf16_split(float v, __nv_bfloat16& h, __nv_bfloat16& l)
{
    h = __float2bfloat16_rn(v);
    l = __float2bfloat16_rn(v - __bfloat162float(h));
}

__device__ __forceinline__ unsigned bf16pack(__nv_bfloat16 a, __nv_bfloat16 b)
{
    __nv_bfloat162 p = __halves2bfloat162(a, b);   // .x (low) = even-k
    return *reinterpret_cast<unsigned*>(&p);
}

__device__ __forceinline__ void split2(float f0, float f1, unsigned& hi, unsigned& lo)
{
    __nv_bfloat16 h0,l0,h1,l1;
    bf16_split(f0, h0, l0); bf16_split(f1, h1, l1);
    hi = bf16pack(h0, h1); lo = bf16pack(l0, l1);
}

template<int STR>
__device__ __forceinline__ void store_row_bf16(
    unsigned (*Hi)[STR], unsigned (*Lo)[STR], int kp0, int m, float4 v)
{
    unsigned h01, l01, h23, l23;
    split2(v.x, v.y, h01, l01);
    split2(v.z, v.w, h23, l23);
    Hi[kp0    ][m] = h01; Lo[kp0    ][m] = l01;
    Hi[kp0 + 1][m] = h23; Lo[kp0 + 1][m] = l23;
}

#define MMA_BF16(D, A, B0, B1)                                                   \
    asm volatile("mma.sync.aligned.m16n8k16.row.col.f32.bf16.bf16.f32 "          \
                 "{%0,%1,%2,%3},{%4,%5,%6,%7},{%8,%9},{%0,%1,%2,%3};"            \
                 : "+f"(D[0]), "+f"(D[1]), "+f"(D[2]), "+f"(D[3])                \
                 : "r"(A[0]), "r"(A[1]), "r"(A[2]), "r"(A[3]), "r"(B0), "r"(B1))

// ---------------- NT GEMM via tensor cores (3xBF16) ----------------
template<int MODE>
__global__ __launch_bounds__(256) void gemm_bf16x3(
    const float* __restrict__ W,
    const float* __restrict__ bias,
    float* __restrict__ Cout)
{
    const float* A = (MODE == 0) ? g_ctx : g_x;
    const int K = DMODEL;

    __shared__ unsigned As_hi[2][8][136], As_lo[2][8][136];
    __shared__ unsigned Ws_hi[2][8][136], Ws_lo[2][8][136];

    const int t    = threadIdx.x;
    const int lane = t & 31;
    const int wid  = t >> 5;
    const int warp_m = wid & 3;
    const int warp_n = wid >> 2;
    const int r = lane >> 2;
    const int c = lane & 3;

    const int row0 = blockIdx.y * 128;
    const int col0 = blockIdx.x * 128;

    const int fm = t >> 2;
    const int kq = (t & 3) * 4;
    const int kp0 = (t & 3) * 2;

    const float* Ap = A + (size_t)(row0 + fm) * K + kq;
    const float* Wp = W + (size_t)(col0 + fm) * K + kq;

    float d[2][8][4];
    #pragma unroll
    for (int i = 0; i < 2; i++)
        #pragma unroll
        for (int j = 0; j < 8; j++)
            #pragma unroll
            for (int e = 0; e < 4; e++) d[i][j][e] = 0.f;

    float4 aR0 = *(const float4*)(Ap);
    float4 aR1 = *(const float4*)(Ap + (size_t)64 * K);
    float4 wR0 = *(const float4*)(Wp);
    float4 wR1 = *(const float4*)(Wp + (size_t)64 * K);

    store_row_bf16<136>(As_hi[0], As_lo[0], kp0, fm,      aR0);
    store_row_bf16<136>(As_hi[0], As_lo[0], kp0, fm + 64, aR1);
    store_row_bf16<136>(Ws_hi[0], Ws_lo[0], kp0, fm,      wR0);
    store_row_bf16<136>(Ws_hi[0], Ws_lo[0], kp0, fm + 64, wR1);
    __syncthreads();

    const int NIT = K / 16;
    for (int it = 0; it < NIT; it++) {
        const int buf = it & 1;
        if (it + 1 < NIT) {
            int k0 = (it + 1) * 16;
            aR0 = *(const float4*)(Ap + k0);
            aR1 = *(const float4*)(Ap + (size_t)64 * K + k0);
            wR0 = *(const float4*)(Wp + k0);
            wR1 = *(const float4*)(Wp + (size_t)64 * K + k0);
        }
        {
            unsigned (*Ah)[136] = As_hi[buf];
            unsigned (*Al)[136] = As_lo[buf];
            unsigned (*Wh)[136] = Ws_hi[buf];
            unsigned (*Wl)[136] = Ws_lo[buf];

            unsigned ah[2][4], al[2][4];
            #pragma unroll
            for (int mt = 0; mt < 2; mt++) {
                int rb = warp_m * 32 + mt * 16 + r;
                ah[mt][0] = Ah[c][rb];     ah[mt][1] = Ah[c][rb + 8];
                ah[mt][2] = Ah[c + 4][rb]; ah[mt][3] = Ah[c + 4][rb + 8];
                al[mt][0] = Al[c][rb];     al[mt][1] = Al[c][rb + 8];
                al[mt][2] = Al[c + 4][rb]; al[mt][3] = Al[c + 4][rb + 8];
            }
            #pragma unroll
            for (int nt = 0; nt < 8; nt++) {
                int nb = warp_n * 64 + nt * 8 + r;
                unsigned b0h = Wh[c][nb], b1h = Wh[c + 4][nb];
                unsigned b0l = Wl[c][nb], b1l = Wl[c + 4][nb];
                #pragma unroll
                for (int mt = 0; mt < 2; mt++) {
                    MMA_BF16(d[mt][nt], ah[mt], b0h, b1h);
                    MMA_BF16(d[mt][nt], ah[mt], b0l, b1l);
                    MMA_BF16(d[mt][nt], al[mt], b0h, b1h);
                }
            }
        }
        if (it + 1 < NIT) {
            int nb = buf ^ 1;
            store_row_bf16<136>(As_hi[nb], As_lo[nb], kp0, fm,      aR0);
            store_row_bf16<136>(As_hi[nb], As_lo[nb], kp0, fm + 64, aR1);
            store_row_bf16<136>(Ws_hi[nb], Ws_lo[nb], kp0, fm,      wR0);
            store_row_bf16<136>(Ws_hi[nb], Ws_lo[nb], kp0, fm + 64, wR1);
        }
        __syncthreads();
    }

    float* Cdst = (MODE == 0) ? Cout : (MODE == 1) ? g_q : (MODE == 2) ? g_k : g_v;
    #pragma unroll
    for (int mt = 0; mt < 2; mt++) {
        int m0 = row0 + warp_m * 32 + mt * 16 + r;
        #pragma unroll
        for (int nt = 0; nt < 8; nt++) {
            int n = col0 + warp_n * 64 + nt * 8 + 2 * c;
            float b0v = bias[n], b1v = bias[n + 1];
            float v00 = d[mt][nt][0] + b0v, v01 = d[mt][nt][1] + b1v;
            float v10 = d[mt][nt][2] + b0v, v11 = d[mt][nt][3] + b1v;
            if (MODE == 0) {
                *(float2*)&Cdst[(size_t)m0 * DMODEL + n]       = make_float2(v00, v01);
                *(float2*)&Cdst[(size_t)(m0 + 8) * DMODEL + n] = make_float2(v10, v11);
            } else {
                int hh = n >> 6, dk = n & 63;
                int b1_ = m0 >> 9,       nq1 = m0 & 511;
                int b2_ = (m0 + 8) >> 9, nq2 = (m0 + 8) & 511;
                *(float2*)&Cdst[(((size_t)(b1_ * NHEAD + hh)) * SEQ + nq1) * DHEAD + dk] = make_float2(v00, v01);
                *(float2*)&Cdst[(((size_t)(b2_ * NHEAD + hh)) * SEQ + nq2) * DHEAD + dk] = make_float2(v10, v11);
            }
        }
    }
}

// ---------------- fused attention: scores + bias + softmax + att-write + PV ----------------
// grid (q-tile=8, bh=192), 256 threads. Dynamic smem holds the full 64x512 score panel.
#define SM_S     0                      // float S[64][520]           133120 B
#define SM_QHI   133120                 // unsigned Qhi[32][72]         9216 B
#define SM_QLO   142336                 // unsigned Qlo[32][72]         9216 B
#define SM_KHI   151552                 // unsigned Khi[32][72]         9216 B (reused as Vhi)
#define SM_KLO   160768                 // unsigned Klo[32][72]         9216 B (reused as Vlo)
#define SM_VST   169984                 // float Vst[64][68]           17408 B
#define SM_EMB   187392                 // float emb[32]                 128 B
#define SM_PXQ   187520                 // int spxq[64]                  256 B
#define SM_PYQ   187776                 // int spyq[64]                  256 B
#define SM_PXK   188032                 // int spxk[512]                2048 B
#define SM_PYK   190080                 // int spyk[512]                2048 B
#define SMEM_ATTN 192128

__global__ __launch_bounds__(256) void fused_attn(
    const float* __restrict__ dist_emb, float* __restrict__ att)
{
    extern __shared__ char smraw[];
    float    (*S)[520]   = (float(*)[520])  (smraw + SM_S);
    unsigned (*Qhi)[72]  = (unsigned(*)[72])(smraw + SM_QHI);
    unsigned (*Qlo)[72]  = (unsigned(*)[72])(smraw + SM_QLO);
    unsigned (*Khi)[72]  = (unsigned(*)[72])(smraw + SM_KHI);
    unsigned (*Klo)[72]  = (unsigned(*)[72])(smraw + SM_KLO);
    float    (*Vst)[68]  = (float(*)[68])   (smraw + SM_VST);
    float*   emb  = (float*)(smraw + SM_EMB);
    int*     spxq = (int*)  (smraw + SM_PXQ);
    int*     spyq = (int*)  (smraw + SM_PYQ);
    int*     spxk = (int*)  (smraw + SM_PXK);
    int*     spyk = (int*)  (smraw + SM_PYK);

    const int t    = threadIdx.x;
    const int lane = t & 31;
    const int wid  = t >> 5;
    const int warp_m = wid & 3;       // 0..3 -> 16 rows each
    const int warp_n = wid >> 2;      // 0..1 -> 32 cols each
    const int r = lane >> 2;          // 0..7
    const int c = lane & 3;           // 0..3

    const int bh = blockIdx.y;
    const int b  = bh / NHEAD, h = bh % NHEAD;
    const int q0 = blockIdx.x * 64;

    const float* Qb = g_q + (size_t)bh * SEQ * DHEAD;
    const float* Kb = g_k + (size_t)bh * SEQ * DHEAD;
    const float* Vb = g_v + (size_t)bh * SEQ * DHEAD;

    // ---- preload small tables + Q tile (convert to bf16 hi/lo [kpair][m]) ----
    if (t < NDIST) emb[t] = dist_emb[t * NHEAD + h];
    if (t < 64) {
        spxq[t] = g_px[b * SEQ + q0 + t];
        spyq[t] = g_py[b * SEQ + q0 + t];
    }
    spxk[t]       = g_px[b * SEQ + t];
    spxk[t + 256] = g_px[b * SEQ + t + 256];
    spyk[t]       = g_py[b * SEQ + t];
    spyk[t + 256] = g_py[b * SEQ + t + 256];

    const int frow = t >> 2;          // 0..63
    const int fcq  = (t & 3) * 16;    // 0,16,32,48
    const int fkp0 = (t & 3) * 8;     // kpair base
    {
        const float* qp = Qb + (size_t)(q0 + frow) * DHEAD + fcq;
        #pragma unroll
        for (int u = 0; u < 4; u++) {
            float4 v = *(const float4*)(qp + u * 4);
            store_row_bf16<72>(Qhi, Qlo, fkp0 + u * 2, frow, v);
        }
    }
    __syncthreads();

    // ---- preload Q fragments (registers, reused for all 8 k-tiles) ----
    const int rb = warp_m * 16 + r;
    unsigned qah[4][4], qal[4][4];
    #pragma unroll
    for (int ks = 0; ks < 4; ks++) {
        qah[ks][0] = Qhi[ks * 8 + c][rb];     qah[ks][1] = Qhi[ks * 8 + c][rb + 8];
        qah[ks][2] = Qhi[ks * 8 + c + 4][rb]; qah[ks][3] = Qhi[ks * 8 + c + 4][rb + 8];
        qal[ks][0] = Qlo[ks * 8 + c][rb];     qal[ks][1] = Qlo[ks * 8 + c][rb + 8];
        qal[ks][2] = Qlo[ks * 8 + c + 4][rb]; qal[ks][3] = Qlo[ks * 8 + c + 4][rb + 8];
    }

    // ---- phase 1: S = QK^T/8 + bias, k-tile by k-tile ----
    for (int kt = 0; kt < 8; kt++) {
        float4 kv[4];
        {
            const float* kp = Kb + (size_t)(kt * 64 + frow) * DHEAD + fcq;
            #pragma unroll
            for (int u = 0; u < 4; u++) kv[u] = *(const float4*)(kp + u * 4);
        }
        __syncthreads();   // prior mma done before overwriting Khi
        #pragma unroll
        for (int u = 0; u < 4; u++)
            store_row_bf16<72>(Khi, Klo, fkp0 + u * 2, frow, kv[u]);
        __syncthreads();

        float d[4][4];
        #pragma unroll
        for (int nt = 0; nt < 4; nt++)
            #pragma unroll
            for (int e = 0; e < 4; e++) d[nt][e] = 0.f;

        #pragma unroll
        for (int ks = 0; ks < 4; ks++) {
            #pragma unroll
            for (int nt = 0; nt < 4; nt++) {
                int nb = warp_n * 32 + nt * 8 + r;
                unsigned b0h = Khi[ks * 8 + c][nb], b1h = Khi[ks * 8 + c + 4][nb];
                unsigned b0l = Klo[ks * 8 + c][nb], b1l = Klo[ks * 8 + c + 4][nb];
                MMA_BF16(d[nt], qah[ks], b0h, b1h);
                MMA_BF16(d[nt], qah[ks], b0l, b1l);
                MMA_BF16(d[nt], qal[ks], b0h, b1h);
            }
        }

        // bias + store to S panel
        int pxq0 = spxq[rb],     pyq0 = spyq[rb];
        int pxq1 = spxq[rb + 8], pyq1 = spyq[rb + 8];
        #pragma unroll
        for (int nt = 0; nt < 4; nt++) {
            int ncol = warp_n * 32 + nt * 8 + 2 * c;      // local col (even)
            int kg   = kt * 64 + ncol;                    // global key
            int pxk0 = spxk[kg],     pyk0 = spyk[kg];
            int pxk1 = spxk[kg + 1], pyk1 = spyk[kg + 1];
            int dx00 = pxk0 - pxq0, dy00 = pyk0 - pyq0;
            int dx01 = pxk1 - pxq0, dy01 = pyk1 - pyq0;
            int dx10 = pxk0 - pxq1, dy10 = pyk0 - pyq1;
            int dx11 = pxk1 - pxq1, dy11 = pyk1 - pyq1;
            float e00 = emb[(int)(sqrtf((float)(dx00*dx00 + dy00*dy00)) * 2.0f)];
            float e01 = emb[(int)(sqrtf((float)(dx01*dx01 + dy01*dy01)) * 2.0f)];
            float e10 = emb[(int)(sqrtf((float)(dx10*dx10 + dy10*dy10)) * 2.0f)];
            float e11 = emb[(int)(sqrtf((float)(dx11*dx11 + dy11*dy11)) * 2.0f)];
            S[rb][kt * 64 + ncol]         = d[nt][0] * 0.125f + e00;
            S[rb][kt * 64 + ncol + 1]     = d[nt][1] * 0.125f + e01;
            S[rb + 8][kt * 64 + ncol]     = d[nt][2] * 0.125f + e10;
            S[rb + 8][kt * 64 + ncol + 1] = d[nt][3] * 0.125f + e11;
        }
    }
    __syncthreads();

    // ---- phase 2: softmax per row (warp handles 8 rows), write att once ----
    for (int rr = 0; rr < 8; rr++) {
        int row = wid * 8 + rr;
        float* Sr = S[row];
        float4 x0 = ((float4*)Sr)[lane];
        float4 x1 = ((float4*)Sr)[lane + 32];
        float4 x2 = ((float4*)Sr)[lane + 64];
        float4 x3 = ((float4*)Sr)[lane + 96];
        float m = fmaxf(fmaxf(fmaxf(x0.x,x0.y),fmaxf(x0.z,x0.w)),
                  fmaxf(fmaxf(fmaxf(x1.x,x1.y),fmaxf(x1.z,x1.w)),
                  fmaxf(fmaxf(fmaxf(x2.x,x2.y),fmaxf(x2.z,x2.w)),
                        fmaxf(fmaxf(x3.x,x3.y),fmaxf(x3.z,x3.w)))));
        #pragma unroll
        for (int o = 16; o > 0; o >>= 1) m = fmaxf(m, __shfl_xor_sync(0xffffffffu, m, o));
        x0.x = expf(x0.x - m); x0.y = expf(x0.y - m); x0.z = expf(x0.z - m); x0.w = expf(x0.w - m);
        x1.x = expf(x1.x - m); x1.y = expf(x1.y - m); x1.z = expf(x1.z - m); x1.w = expf(x1.w - m);
        x2.x = expf(x2.x - m); x2.y = expf(x2.y - m); x2.z = expf(x2.z - m); x2.w = expf(x2.w - m);
        x3.x = expf(x3.x - m); x3.y = expf(x3.y - m); x3.z = expf(x3.z - m); x3.w = expf(x3.w - m);
        float s = (x0.x+x0.y+x0.z+x0.w) + (x1.x+x1.y+x1.z+x1.w)
                + (x2.x+x2.y+x2.z+x2.w) + (x3.x+x3.y+x3.z+x3.w);
        #pragma unroll
        for (int o = 16; o > 0; o >>= 1) s += __shfl_xor_sync(0xffffffffu, s, o);
        float inv = 1.0f / s;
        x0.x*=inv; x0.y*=inv; x0.z*=inv; x0.w*=inv;
        x1.x*=inv; x1.y*=inv; x1.z*=inv; x1.w*=inv;
        x2.x*=inv; x2.y*=inv; x2.z*=inv; x2.w*=inv;
        x3.x*=inv; x3.y*=inv; x3.z*=inv; x3.w*=inv;
        ((float4*)Sr)[lane]      = x0;
        ((float4*)Sr)[lane + 32] = x1;
        ((float4*)Sr)[lane + 64] = x2;
        ((float4*)Sr)[lane + 96] = x3;
        float* ar = att + ((size_t)bh * SEQ + q0 + row) * SEQ;
        ((float4*)ar)[lane]      = x0;
        ((float4*)ar)[lane + 32] = x1;
        ((float4*)ar)[lane + 64] = x2;
        ((float4*)ar)[lane + 96] = x3;
    }
    __syncthreads();

    // ---- phase 3: ctx = P @ V (3xBF16, A from S on the fly) ----
    unsigned (*Vhi)[72] = Khi;
    unsigned (*Vlo)[72] = Klo;
    float ctx[4][4];
    #pragma unroll
    for (int nt = 0; nt < 4; nt++)
        #pragma unroll
        for (int e = 0; e < 4; e++) ctx[nt][e] = 0.f;

    for (int kt = 0; kt < 8; kt++) {
        float4 vv[4];
        {
            const float* vp = Vb + (size_t)(kt * 64 + frow) * DHEAD + fcq;
            #pragma unroll
            for (int u = 0; u < 4; u++) vv[u] = *(const float4*)(vp + u * 4);
        }
        __syncthreads();   // prior mma done before Vst/Vhi overwrite
        #pragma unroll
        for (int u = 0; u < 4; u++)
            *(float4*)&Vst[frow][fcq + u * 4] = vv[u];
        __syncthreads();
        // convert Vst -> Vhi/Vlo [kpair over keys][d]
        #pragma unroll
        for (int i = 0; i < 8; i++) {
            int flat = t + i * 256;          // 0..2047
            int kp = flat >> 6, dcol = flat & 63;
            unsigned hi, lo;
            split2(Vst[2 * kp][dcol], Vst[2 * kp + 1][dcol], hi, lo);
            Vhi[kp][dcol] = hi;
            Vlo[kp][dcol] = lo;
        }
        __syncthreads();

        #pragma unroll
        for (int ks = 0; ks < 4; ks++) {
            int kbase = kt * 64 + ks * 16;
            float f00 = S[rb][kbase + 2*c],     f01 = S[rb][kbase + 2*c + 1];
            float f10 = S[rb + 8][kbase + 2*c], f11 = S[rb + 8][kbase + 2*c + 1];
            float f20 = S[rb][kbase + 8 + 2*c],     f21 = S[rb][kbase + 8 + 2*c + 1];
            float f30 = S[rb + 8][kbase + 8 + 2*c], f31 = S[rb + 8][kbase + 8 + 2*c + 1];
            unsigned ah[4], al[4];
            split2(f00, f01, ah[0], al[0]);
            split2(f10, f11, ah[1], al[1]);
            split2(f20, f21, ah[2], al[2]);
            split2(f30, f31, ah[3], al[3]);
            #pragma unroll
            for (int nt = 0; nt < 4; nt++) {
                int nb = warp_n * 32 + nt * 8 + r;
                unsigned b0h = Vhi[ks * 8 + c][nb], b1h = Vhi[ks * 8 + c + 4][nb];
                unsigned b0l = Vlo[ks * 8 + c][nb], b1l = Vlo[ks * 8 + c + 4][nb];
                MMA_BF16(ctx[nt], ah, b0h, b1h);
                MMA_BF16(ctx[nt], ah, b0l, b1l);
                MMA_BF16(ctx[nt], al, b0h, b1h);
            }
        }
    }

    // ---- epilogue: write ctx (B,N,H*DK) ----
    #pragma unroll
    for (int nt = 0; nt < 4; nt++) {
        int q1 = q0 + rb;
        int dcol = warp_n * 32 + nt * 8 + 2 * c;
        *(float2*)&g_ctx[((size_t)(b * SEQ + q1)) * DMODEL + h * DHEAD + dcol] =
            make_float2(ctx[nt][0], ctx[nt][1]);
        *(float2*)&g_ctx[((size_t)(b * SEQ + q1 + 8)) * DMODEL + h * DHEAD + dcol] =
            make_float2(ctx[nt][2], ctx[nt][3]);
    }
}

// ---------------- launch ----------------
extern "C" void kernel_launch(void* const* d_in, const int* in_sizes, int n_in,
                              void* d_out, int out_size)
{
    const float* features    = (const float*)d_in[0];
    const float* boxes       = (const float*)d_in[1];
    const int*   image_sizes = (const int*)  d_in[2];
    const float* Wq    = (const float*)d_in[3];
    const float* bq    = (const float*)d_in[4];
    const float* Wk    = (const float*)d_in[5];
    const float* bk    = (const float*)d_in[6];
    const float* Wv    = (const float*)d_in[7];
    const float* bv    = (const float*)d_in[8];
    const float* Wo    = (const float*)d_in[9];
    const float* bo    = (const float*)d_in[10];
    const float* gamma = (const float*)d_in[11];
    const float* beta  = (const float*)d_in[12];
    const float* demb  = (const float*)d_in[13];

    float* out = (float*)d_out;
    float* att = out + (size_t)BATCH * SEQ * DMODEL;

    cudaFuncSetAttribute(fused_attn, cudaFuncAttributeMaxDynamicSharedMemorySize, SMEM_ATTN);

    const int M = BATCH * SEQ;   // 8192

    ln_kernel<<<M, 256>>>(features, gamma, beta);
    bins_kernel<<<(M + 255) / 256, 256>>>(boxes, image_sizes);

    dim3 gProj(DMODEL / 128, M / 128);   // (6, 64)
    gemm_bf16x3<1><<<gProj, 256>>>(Wq, bq, nullptr);
    gemm_bf16x3<2><<<gProj, 256>>>(Wk, bk, nullptr);
    gemm_bf16x3<3><<<gProj, 256>>>(Wv, bv, nullptr);

    fused_attn<<<dim3(SEQ / 64, BATCH * NHEAD), 256, SMEM_ATTN>>>(demb, att);

    gemm_bf16x3<0><<<gProj, 256>>>(Wo, bo, out);
}

// round 11
// speedup vs baseline: 2.1547x; 1.1113x over previous
#include <cuda_runtime.h>
#include <cuda_bf16.h>
#include <math.h>

#define BATCH  16
#define SEQ    512
#define DMODEL 768
#define NHEAD  12
#define DHEAD  64
#define NDIST  32

// ---------------- scratch (static device memory; referenced by symbol only) ----------------
__device__ float g_x  [BATCH*SEQ*DMODEL];
__device__ float g_q  [BATCH*SEQ*DMODEL];   // layout (B,H,N,DK)
__device__ float g_k  [BATCH*SEQ*DMODEL];   // layout (B,H,N,DK)
__device__ float g_v  [BATCH*SEQ*DMODEL];   // layout (B,H,N,DK)
__device__ float g_ctx[BATCH*SEQ*DMODEL];   // layout (B,N,H*DK)
__device__ int   g_px [BATCH*SEQ];
__device__ int   g_py [BATCH*SEQ];

// ---------------- LayerNorm ----------------
__global__ __launch_bounds__(256) void ln_kernel(
    const float* __restrict__ feat,
    const float* __restrict__ gamma,
    const float* __restrict__ beta)
{
    int row = blockIdx.x;
    const float* x = feat + (size_t)row * DMODEL;
    float* y = g_x + (size_t)row * DMODEL;
    int t = threadIdx.x;

    float v0 = x[t], v1 = x[t + 256], v2 = x[t + 512];
    float s  = v0 + v1 + v2;
    float q  = v0*v0 + v1*v1 + v2*v2;

    __shared__ float ss[8], sq[8];
    #pragma unroll
    for (int o = 16; o > 0; o >>= 1) {
        s += __shfl_xor_sync(0xffffffffu, s, o);
        q += __shfl_xor_sync(0xffffffffu, q, o);
    }
    if ((t & 31) == 0) { ss[t >> 5] = s; sq[t >> 5] = q; }
    __syncthreads();
    if (t == 0) {
        float a = 0.f, b2 = 0.f;
        #pragma unroll
        for (int i = 0; i < 8; i++) { a += ss[i]; b2 += sq[i]; }
        ss[0] = a; sq[0] = b2;
    }
    __syncthreads();
    float mean = ss[0] * (1.0f / DMODEL);
    float var  = sq[0] * (1.0f / DMODEL) - mean * mean;
    float inv  = rsqrtf(var + 1e-5f);

    y[t]       = (v0 - mean) * inv * gamma[t]       + beta[t];
    y[t + 256] = (v1 - mean) * inv * gamma[t + 256] + beta[t + 256];
    y[t + 512] = (v2 - mean) * inv * gamma[t + 512] + beta[t + 512];
}

// ---------------- patch bins (exact replica of reference semantics) ----------------
__global__ void bins_kernel(
    const float* __restrict__ boxes,
    const int* __restrict__ image_sizes)
{
    int idx = blockIdx.x * blockDim.x + threadIdx.x;
    if (idx >= BATCH * SEQ) return;
    int b = idx / SEQ;
    float w = (float)image_sizes[b * 4 + 0];
    float h = (float)image_sizes[b * 4 + 1];
    const float* bx = boxes + (size_t)idx * 4;
    float x0 = bx[0] * w, y0 = bx[1] * h, x1 = bx[2] * w, y1 = bx[3] * h;
    float spaw = floorf(w / 11.0f);
    float spah = floorf(h / 11.0f);
    float cx = floorf((x0 + x1) / 2.0f);
    float cy = floorf((y0 + y1) / 2.0f);
    int pxv = 0, pyv = 0;
    for (int j = 10; j >= 0; j--) {
        float lbw = (float)j * spaw, hbw = (float)(j + 1) * spaw;
        if (lbw <= cx && cx <= hbw) pxv = j;
        float lbh = (float)j * spah, hbh = (float)(j + 1) * spah;
        if (lbh <= cy && cy <= hbh) pyv = j;
    }
    g_px[idx] = pxv;
    g_py[idx] = pyv;
}

// ---------------- bf16 3x helpers ----------------
__device__ __forceinline__ void bf16_split(float v, __nv_bfloat16& h, __nv_bfloat16& l)
{
    h = __float2bfloat16_rn(v);
    l = __float2bfloat16_rn(v - __bfloat162float(h));
}

__device__ __forceinline__ unsigned bf16pack(__nv_bfloat16 a, __nv_bfloat16 b)
{
    __nv_bfloat162 p = __halves2bfloat162(a, b);   // .x (low) = even-k
    return *reinterpret_cast<unsigned*>(&p);
}

__device__ __forceinline__ void split2(float f0, float f1, unsigned& hi, unsigned& lo)
{
    __nv_bfloat16 h0,l0,h1,l1;
    bf16_split(f0, h0, l0); bf16_split(f1, h1, l1);
    hi = bf16pack(h0, h1); lo = bf16pack(l0, l1);
}

template<int STR>
__device__ __forceinline__ void store_row_bf16(
    unsigned (*Hi)[STR], unsigned (*Lo)[STR], int kp0, int m, float4 v)
{
    unsigned h01, l01, h23, l23;
    split2(v.x, v.y, h01, l01);
    split2(v.z, v.w, h23, l23);
    Hi[kp0    ][m] = h01; Lo[kp0    ][m] = l01;
    Hi[kp0 + 1][m] = h23; Lo[kp0 + 1][m] = l23;
}

#define MMA_BF16(D, A, B0, B1)                                                   \
    asm volatile("mma.sync.aligned.m16n8k16.row.col.f32.bf16.bf16.f32 "          \
                 "{%0,%1,%2,%3},{%4,%5,%6,%7},{%8,%9},{%0,%1,%2,%3};"            \
                 : "+f"(D[0]), "+f"(D[1]), "+f"(D[2]), "+f"(D[3])                \
                 : "r"(A[0]), "r"(A[1]), "r"(A[2]), "r"(A[3]), "r"(B0), "r"(B1))

// ---------------- shared GEMM body (3xBF16, NT, 128x128 tile) ----------------
// A row-major [.,768], W row-major [768,768]; C = A @ W^T + bias.
// SCATTER=1: write to (B,H,N,DK) layout; SCATTER=0: row-major.
template<int SCATTER>
__device__ __forceinline__ void gemm_body(
    const float* __restrict__ A, const float* __restrict__ W,
    const float* __restrict__ bias, float* __restrict__ Cdst,
    int row0, int col0)
{
    const int K = DMODEL;
    __shared__ unsigned As_hi[2][8][136], As_lo[2][8][136];
    __shared__ unsigned Ws_hi[2][8][136], Ws_lo[2][8][136];

    const int t    = threadIdx.x;
    const int lane = t & 31;
    const int wid  = t >> 5;
    const int warp_m = wid & 3;
    const int warp_n = wid >> 2;
    const int r = lane >> 2;
    const int c = lane & 3;

    const int fm = t >> 2;
    const int kq = (t & 3) * 4;
    const int kp0 = (t & 3) * 2;

    const float* Ap = A + (size_t)(row0 + fm) * K + kq;
    const float* Wp = W + (size_t)(col0 + fm) * K + kq;

    float d[2][8][4];
    #pragma unroll
    for (int i = 0; i < 2; i++)
        #pragma unroll
        for (int j = 0; j < 8; j++)
            #pragma unroll
            for (int e = 0; e < 4; e++) d[i][j][e] = 0.f;

    float4 aR0 = *(const float4*)(Ap);
    float4 aR1 = *(const float4*)(Ap + (size_t)64 * K);
    float4 wR0 = *(const float4*)(Wp);
    float4 wR1 = *(const float4*)(Wp + (size_t)64 * K);

    store_row_bf16<136>(As_hi[0], As_lo[0], kp0, fm,      aR0);
    store_row_bf16<136>(As_hi[0], As_lo[0], kp0, fm + 64, aR1);
    store_row_bf16<136>(Ws_hi[0], Ws_lo[0], kp0, fm,      wR0);
    store_row_bf16<136>(Ws_hi[0], Ws_lo[0], kp0, fm + 64, wR1);
    __syncthreads();

    const int NIT = K / 16;
    for (int it = 0; it < NIT; it++) {
        const int buf = it & 1;
        if (it + 1 < NIT) {
            int k0 = (it + 1) * 16;
            aR0 = *(const float4*)(Ap + k0);
            aR1 = *(const float4*)(Ap + (size_t)64 * K + k0);
            wR0 = *(const float4*)(Wp + k0);
            wR1 = *(const float4*)(Wp + (size_t)64 * K + k0);
        }
        {
            unsigned (*Ah)[136] = As_hi[buf];
            unsigned (*Al)[136] = As_lo[buf];
            unsigned (*Wh)[136] = Ws_hi[buf];
            unsigned (*Wl)[136] = Ws_lo[buf];

            unsigned ah[2][4], al[2][4];
            #pragma unroll
            for (int mt = 0; mt < 2; mt++) {
                int rb = warp_m * 32 + mt * 16 + r;
                ah[mt][0] = Ah[c][rb];     ah[mt][1] = Ah[c][rb + 8];
                ah[mt][2] = Ah[c + 4][rb]; ah[mt][3] = Ah[c + 4][rb + 8];
                al[mt][0] = Al[c][rb];     al[mt][1] = Al[c][rb + 8];
                al[mt][2] = Al[c + 4][rb]; al[mt][3] = Al[c + 4][rb + 8];
            }
            #pragma unroll
            for (int nt = 0; nt < 8; nt++) {
                int nb = warp_n * 64 + nt * 8 + r;
                unsigned b0h = Wh[c][nb], b1h = Wh[c + 4][nb];
                unsigned b0l = Wl[c][nb], b1l = Wl[c + 4][nb];
                #pragma unroll
                for (int mt = 0; mt < 2; mt++) {
                    MMA_BF16(d[mt][nt], ah[mt], b0h, b1h);
                    MMA_BF16(d[mt][nt], ah[mt], b0l, b1l);
                    MMA_BF16(d[mt][nt], al[mt], b0h, b1h);
                }
            }
        }
        if (it + 1 < NIT) {
            int nb = buf ^ 1;
            store_row_bf16<136>(As_hi[nb], As_lo[nb], kp0, fm,      aR0);
            store_row_bf16<136>(As_hi[nb], As_lo[nb], kp0, fm + 64, aR1);
            store_row_bf16<136>(Ws_hi[nb], Ws_lo[nb], kp0, fm,      wR0);
            store_row_bf16<136>(Ws_hi[nb], Ws_lo[nb], kp0, fm + 64, wR1);
        }
        __syncthreads();
    }

    #pragma unroll
    for (int mt = 0; mt < 2; mt++) {
        int m0 = row0 + warp_m * 32 + mt * 16 + r;
        #pragma unroll
        for (int nt = 0; nt < 8; nt++) {
            int n = col0 + warp_n * 64 + nt * 8 + 2 * c;
            float b0v = bias[n], b1v = bias[n + 1];
            float v00 = d[mt][nt][0] + b0v, v01 = d[mt][nt][1] + b1v;
            float v10 = d[mt][nt][2] + b0v, v11 = d[mt][nt][3] + b1v;
            if (SCATTER == 0) {
                *(float2*)&Cdst[(size_t)m0 * DMODEL + n]       = make_float2(v00, v01);
                *(float2*)&Cdst[(size_t)(m0 + 8) * DMODEL + n] = make_float2(v10, v11);
            } else {
                int hh = n >> 6, dk = n & 63;
                int b1_ = m0 >> 9,       nq1 = m0 & 511;
                int b2_ = (m0 + 8) >> 9, nq2 = (m0 + 8) & 511;
                *(float2*)&Cdst[(((size_t)(b1_ * NHEAD + hh)) * SEQ + nq1) * DHEAD + dk] = make_float2(v00, v01);
                *(float2*)&Cdst[(((size_t)(b2_ * NHEAD + hh)) * SEQ + nq2) * DHEAD + dk] = make_float2(v10, v11);
            }
        }
    }
}

// QKV in one launch: blockIdx.z selects projection
__global__ __launch_bounds__(256) void gemm_qkv(
    const float* __restrict__ Wq, const float* __restrict__ Wk, const float* __restrict__ Wv,
    const float* __restrict__ bq, const float* __restrict__ bk, const float* __restrict__ bv)
{
    const float* W    = (blockIdx.z == 0) ? Wq : (blockIdx.z == 1) ? Wk : Wv;
    const float* bias = (blockIdx.z == 0) ? bq : (blockIdx.z == 1) ? bk : bv;
    float* Cdst       = (blockIdx.z == 0) ? g_q : (blockIdx.z == 1) ? g_k : g_v;
    gemm_body<1>(g_x, W, bias, Cdst, blockIdx.y * 128, blockIdx.x * 128);
}

// out-projection
__global__ __launch_bounds__(256) void gemm_out(
    const float* __restrict__ Wo, const float* __restrict__ bo, float* __restrict__ out)
{
    gemm_body<0>(g_ctx, Wo, bo, out, blockIdx.y * 128, blockIdx.x * 128);
}

// ---------------- fused attention: scores + bias + softmax + att-write + PV ----------------
// grid (q-tile=8, bh=192), 512 threads = 16 warps. Full 64x512 score panel in dynamic smem.
#define SM_S     0                      // float S[64][520]           133120 B
#define SM_QHI   133120                 // unsigned Qhi[32][72]         9216 B
#define SM_QLO   142336                 // unsigned Qlo[32][72]         9216 B
#define SM_KHI   151552                 // unsigned Khi[32][72]         9216 B (reused as Vhi)
#define SM_KLO   160768                 // unsigned Klo[32][72]         9216 B (reused as Vlo)
#define SM_VST   169984                 // float Vst[64][68]           17408 B
#define SM_EMB   187392                 // float emb[32]                 128 B
#define SM_PXQ   187520                 // int spxq[64]                  256 B
#define SM_PYQ   187776                 // int spyq[64]                  256 B
#define SM_PXK   188032                 // int spxk[512]                2048 B
#define SM_PYK   190080                 // int spyk[512]                2048 B
#define SMEM_ATTN 192128

__global__ __launch_bounds__(512) void fused_attn(
    const float* __restrict__ dist_emb, float* __restrict__ att)
{
    extern __shared__ char smraw[];
    float    (*S)[520]   = (float(*)[520])  (smraw + SM_S);
    unsigned (*Qhi)[72]  = (unsigned(*)[72])(smraw + SM_QHI);
    unsigned (*Qlo)[72]  = (unsigned(*)[72])(smraw + SM_QLO);
    unsigned (*Khi)[72]  = (unsigned(*)[72])(smraw + SM_KHI);
    unsigned (*Klo)[72]  = (unsigned(*)[72])(smraw + SM_KLO);
    float    (*Vst)[68]  = (float(*)[68])   (smraw + SM_VST);
    float*   emb  = (float*)(smraw + SM_EMB);
    int*     spxq = (int*)  (smraw + SM_PXQ);
    int*     spyq = (int*)  (smraw + SM_PYQ);
    int*     spxk = (int*)  (smraw + SM_PXK);
    int*     spyk = (int*)  (smraw + SM_PYK);

    const int t    = threadIdx.x;
    const int lane = t & 31;
    const int wid  = t >> 5;          // 0..15
    const int warp_m = wid & 3;       // 0..3 -> rows warp_m*16 + {r, r+8}
    const int warp_n = wid >> 2;      // 0..3 -> 16 cols each
    const int r = lane >> 2;          // 0..7
    const int c = lane & 3;           // 0..3

    const int bh = blockIdx.y;
    const int b  = bh / NHEAD, h = bh % NHEAD;
    const int q0 = blockIdx.x * 64;

    const float* Qb = g_q + (size_t)bh * SEQ * DHEAD;
    const float* Kb = g_k + (size_t)bh * SEQ * DHEAD;
    const float* Vb = g_v + (size_t)bh * SEQ * DHEAD;

    // ---- preload small tables + Q tile ----
    if (t < NDIST) emb[t] = dist_emb[t * NHEAD + h];
    if (t < 64) {
        spxq[t] = g_px[b * SEQ + q0 + t];
        spyq[t] = g_py[b * SEQ + q0 + t];
    }
    spxk[t] = g_px[b * SEQ + t];
    spyk[t] = g_py[b * SEQ + t];

    const int frow = t >> 3;          // 0..63
    const int fcq  = (t & 7) * 8;     // 0..56 step 8
    const int fkp0 = (t & 7) * 4;     // kpair base
    {
        const float* qp = Qb + (size_t)(q0 + frow) * DHEAD + fcq;
        #pragma unroll
        for (int u = 0; u < 2; u++) {
            float4 v = *(const float4*)(qp + u * 4);
            store_row_bf16<72>(Qhi, Qlo, fkp0 + u * 2, frow, v);
        }
    }
    __syncthreads();

    // ---- preload Q fragments ----
    const int rb = warp_m * 16 + r;
    unsigned qah[4][4], qal[4][4];
    #pragma unroll
    for (int ks = 0; ks < 4; ks++) {
        qah[ks][0] = Qhi[ks * 8 + c][rb];     qah[ks][1] = Qhi[ks * 8 + c][rb + 8];
        qah[ks][2] = Qhi[ks * 8 + c + 4][rb]; qah[ks][3] = Qhi[ks * 8 + c + 4][rb + 8];
        qal[ks][0] = Qlo[ks * 8 + c][rb];     qal[ks][1] = Qlo[ks * 8 + c][rb + 8];
        qal[ks][2] = Qlo[ks * 8 + c + 4][rb]; qal[ks][3] = Qlo[ks * 8 + c + 4][rb + 8];
    }

    // ---- phase 1: S = QK^T/8 + bias ----
    for (int kt = 0; kt < 8; kt++) {
        float4 kv[2];
        {
            const float* kp = Kb + (size_t)(kt * 64 + frow) * DHEAD + fcq;
            #pragma unroll
            for (int u = 0; u < 2; u++) kv[u] = *(const float4*)(kp + u * 4);
        }
        __syncthreads();
        #pragma unroll
        for (int u = 0; u < 2; u++)
            store_row_bf16<72>(Khi, Klo, fkp0 + u * 2, frow, kv[u]);
        __syncthreads();

        float d[2][4];
        #pragma unroll
        for (int nt = 0; nt < 2; nt++)
            #pragma unroll
            for (int e = 0; e < 4; e++) d[nt][e] = 0.f;

        #pragma unroll
        for (int ks = 0; ks < 4; ks++) {
            #pragma unroll
            for (int nt = 0; nt < 2; nt++) {
                int nb = warp_n * 16 + nt * 8 + r;
                unsigned b0h = Khi[ks * 8 + c][nb], b1h = Khi[ks * 8 + c + 4][nb];
                unsigned b0l = Klo[ks * 8 + c][nb], b1l = Klo[ks * 8 + c + 4][nb];
                MMA_BF16(d[nt], qah[ks], b0h, b1h);
                MMA_BF16(d[nt], qah[ks], b0l, b1l);
                MMA_BF16(d[nt], qal[ks], b0h, b1h);
            }
        }

        int pxq0 = spxq[rb],     pyq0 = spyq[rb];
        int pxq1 = spxq[rb + 8], pyq1 = spyq[rb + 8];
        #pragma unroll
        for (int nt = 0; nt < 2; nt++) {
            int ncol = warp_n * 16 + nt * 8 + 2 * c;
            int kg   = kt * 64 + ncol;
            int pxk0 = spxk[kg],     pyk0 = spyk[kg];
            int pxk1 = spxk[kg + 1], pyk1 = spyk[kg + 1];
            int dx00 = pxk0 - pxq0, dy00 = pyk0 - pyq0;
            int dx01 = pxk1 - pxq0, dy01 = pyk1 - pyq0;
            int dx10 = pxk0 - pxq1, dy10 = pyk0 - pyq1;
            int dx11 = pxk1 - pxq1, dy11 = pyk1 - pyq1;
            float e00 = emb[(int)(sqrtf((float)(dx00*dx00 + dy00*dy00)) * 2.0f)];
            float e01 = emb[(int)(sqrtf((float)(dx01*dx01 + dy01*dy01)) * 2.0f)];
            float e10 = emb[(int)(sqrtf((float)(dx10*dx10 + dy10*dy10)) * 2.0f)];
            float e11 = emb[(int)(sqrtf((float)(dx11*dx11 + dy11*dy11)) * 2.0f)];
            S[rb][kg]         = d[nt][0] * 0.125f + e00;
            S[rb][kg + 1]     = d[nt][1] * 0.125f + e01;
            S[rb + 8][kg]     = d[nt][2] * 0.125f + e10;
            S[rb + 8][kg + 1] = d[nt][3] * 0.125f + e11;
        }
    }
    __syncthreads();

    // ---- phase 2: softmax per row (warp handles 4 rows), write att once ----
    for (int rr = 0; rr < 4; rr++) {
        int row = wid * 4 + rr;
        float* Sr = S[row];
        float4 x0 = ((float4*)Sr)[lane];
        float4 x1 = ((float4*)Sr)[lane + 32];
        float4 x2 = ((float4*)Sr)[lane + 64];
        float4 x3 = ((float4*)Sr)[lane + 96];
        float m = fmaxf(fmaxf(fmaxf(x0.x,x0.y),fmaxf(x0.z,x0.w)),
                  fmaxf(fmaxf(fmaxf(x1.x,x1.y),fmaxf(x1.z,x1.w)),
                  fmaxf(fmaxf(fmaxf(x2.x,x2.y),fmaxf(x2.z,x2.w)),
                        fmaxf(fmaxf(x3.x,x3.y),fmaxf(x3.z,x3.w)))));
        #pragma unroll
        for (int o = 16; o > 0; o >>= 1) m = fmaxf(m, __shfl_xor_sync(0xffffffffu, m, o));
        x0.x = __expf(x0.x - m); x0.y = __expf(x0.y - m); x0.z = __expf(x0.z - m); x0.w = __expf(x0.w - m);
        x1.x = __expf(x1.x - m); x1.y = __expf(x1.y - m); x1.z = __expf(x1.z - m); x1.w = __expf(x1.w - m);
        x2.x = __expf(x2.x - m); x2.y = __expf(x2.y - m); x2.z = __expf(x2.z - m); x2.w = __expf(x2.w - m);
        x3.x = __expf(x3.x - m); x3.y = __expf(x3.y - m); x3.z = __expf(x3.z - m); x3.w = __expf(x3.w - m);
        float s = (x0.x+x0.y+x0.z+x0.w) + (x1.x+x1.y+x1.z+x1.w)
                + (x2.x+x2.y+x2.z+x2.w) + (x3.x+x3.y+x3.z+x3.w);
        #pragma unroll
        for (int o = 16; o > 0; o >>= 1) s += __shfl_xor_sync(0xffffffffu, s, o);
        float inv = 1.0f / s;
        x0.x*=inv; x0.y*=inv; x0.z*=inv; x0.w*=inv;
        x1.x*=inv; x1.y*=inv; x1.z*=inv; x1.w*=inv;
        x2.x*=inv; x2.y*=inv; x2.z*=inv; x2.w*=inv;
        x3.x*=inv; x3.y*=inv; x3.z*=inv; x3.w*=inv;
        ((float4*)Sr)[lane]      = x0;
        ((float4*)Sr)[lane + 32] = x1;
        ((float4*)Sr)[lane + 64] = x2;
        ((float4*)Sr)[lane + 96] = x3;
        float* ar = att + ((size_t)bh * SEQ + q0 + row) * SEQ;
        ((float4*)ar)[lane]      = x0;
        ((float4*)ar)[lane + 32] = x1;
        ((float4*)ar)[lane + 64] = x2;
        ((float4*)ar)[lane + 96] = x3;
    }
    __syncthreads();

    // ---- phase 3: ctx = P @ V ----
    unsigned (*Vhi)[72] = Khi;
    unsigned (*Vlo)[72] = Klo;
    float ctx[2][4];
    #pragma unroll
    for (int nt = 0; nt < 2; nt++)
        #pragma unroll
        for (int e = 0; e < 4; e++) ctx[nt][e] = 0.f;

    for (int kt = 0; kt < 8; kt++) {
        float4 vv[2];
        {
            const float* vp = Vb + (size_t)(kt * 64 + frow) * DHEAD + fcq;
            #pragma unroll
            for (int u = 0; u < 2; u++) vv[u] = *(const float4*)(vp + u * 4);
        }
        __syncthreads();
        #pragma unroll
        for (int u = 0; u < 2; u++)
            *(float4*)&Vst[frow][fcq + u * 4] = vv[u];
        __syncthreads();
        // convert Vst -> Vhi/Vlo [kpair over keys][d]
        #pragma unroll
        for (int i = 0; i < 4; i++) {
            int flat = t + i * 512;          // 0..2047
            int kp = flat >> 6, dcol = flat & 63;
            unsigned hi, lo;
            split2(Vst[2 * kp][dcol], Vst[2 * kp + 1][dcol], hi, lo);
            Vhi[kp][dcol] = hi;
            Vlo[kp][dcol] = lo;
        }
        __syncthreads();

        #pragma unroll
        for (int ks = 0; ks < 4; ks++) {
            int kbase = kt * 64 + ks * 16;
            float f00 = S[rb][kbase + 2*c],         f01 = S[rb][kbase + 2*c + 1];
            float f10 = S[rb + 8][kbase + 2*c],     f11 = S[rb + 8][kbase + 2*c + 1];
            float f20 = S[rb][kbase + 8 + 2*c],     f21 = S[rb][kbase + 8 + 2*c + 1];
            float f30 = S[rb + 8][kbase + 8 + 2*c], f31 = S[rb + 8][kbase + 8 + 2*c + 1];
            unsigned ah[4], al[4];
            split2(f00, f01, ah[0], al[0]);
            split2(f10, f11, ah[1], al[1]);
            split2(f20, f21, ah[2], al[2]);
            split2(f30, f31, ah[3], al[3]);
            #pragma unroll
            for (int nt = 0; nt < 2; nt++) {
                int nb = warp_n * 16 + nt * 8 + r;
                unsigned b0h = Vhi[ks * 8 + c][nb], b1h = Vhi[ks * 8 + c + 4][nb];
                unsigned b0l = Vlo[ks * 8 + c][nb], b1l = Vlo[ks * 8 + c + 4][nb];
                MMA_BF16(ctx[nt], ah, b0h, b1h);
                MMA_BF16(ctx[nt], ah, b0l, b1l);
                MMA_BF16(ctx[nt], al, b0h, b1h);
            }
        }
    }

    // ---- epilogue ----
    #pragma unroll
    for (int nt = 0; nt < 2; nt++) {
        int q1 = q0 + rb;
        int dcol = warp_n * 16 + nt * 8 + 2 * c;
        *(float2*)&g_ctx[((size_t)(b * SEQ + q1)) * DMODEL + h * DHEAD + dcol] =
            make_float2(ctx[nt][0], ctx[nt][1]);
        *(float2*)&g_ctx[((size_t)(b * SEQ + q1 + 8)) * DMODEL + h * DHEAD + dcol] =
            make_float2(ctx[nt][2], ctx[nt][3]);
    }
}

// ---------------- launch ----------------
extern "C" void kernel_launch(void* const* d_in, const int* in_sizes, int n_in,
                              void* d_out, int out_size)
{
    const float* features    = (const float*)d_in[0];
    const float* boxes       = (const float*)d_in[1];
    const int*   image_sizes = (const int*)  d_in[2];
    const float* Wq    = (const float*)d_in[3];
    const float* bq    = (const float*)d_in[4];
    const float* Wk    = (const float*)d_in[5];
    const float* bk    = (const float*)d_in[6];
    const float* Wv    = (const float*)d_in[7];
    const float* bv    = (const float*)d_in[8];
    const float* Wo    = (const float*)d_in[9];
    const float* bo    = (const float*)d_in[10];
    const float* gamma = (const float*)d_in[11];
    const float* beta  = (const float*)d_in[12];
    const float* demb  = (const float*)d_in[13];

    float* out = (float*)d_out;
    float* att = out + (size_t)BATCH * SEQ * DMODEL;

    cudaFuncSetAttribute(fused_attn, cudaFuncAttributeMaxDynamicSharedMemorySize, SMEM_ATTN);

    const int M = BATCH * SEQ;   // 8192

    ln_kernel<<<M, 256>>>(features, gamma, beta);
    bins_kernel<<<(M + 255) / 256, 256>>>(boxes, image_sizes);

    gemm_qkv<<<dim3(DMODEL / 128, M / 128, 3), 256>>>(Wq, Wk, Wv, bq, bk, bv);

    fused_attn<<<dim3(SEQ / 64, BATCH * NHEAD), 512, SMEM_ATTN>>>(demb, att);

    gemm_out<<<dim3(DMODEL / 128, M / 128), 256>>>(Wo, bo, out);
}

// round 12
// speedup vs baseline: 2.2387x; 1.0390x over previous
#include <cuda_runtime.h>
#include <cuda_bf16.h>
#include <math.h>

#define BATCH  16
#define SEQ    512
#define DMODEL 768
#define NHEAD  12
#define DHEAD  64
#define NDIST  32

// ---------------- scratch (static device memory; referenced by symbol only) ----------------
__device__ float g_x  [BATCH*SEQ*DMODEL];
__device__ float g_q  [BATCH*SEQ*DMODEL];   // layout (B,H,N,DK)
__device__ float g_k  [BATCH*SEQ*DMODEL];   // layout (B,H,N,DK)
__device__ float g_v  [BATCH*SEQ*DMODEL];   // layout (B,H,N,DK)
__device__ float g_ctx[BATCH*SEQ*DMODEL];   // layout (B,N,H*DK)
__device__ int   g_px [BATCH*SEQ];
__device__ int   g_py [BATCH*SEQ];

// ---------------- LayerNorm ----------------
__global__ __launch_bounds__(256) void ln_kernel(
    const float* __restrict__ feat,
    const float* __restrict__ gamma,
    const float* __restrict__ beta)
{
    int row = blockIdx.x;
    const float* x = feat + (size_t)row * DMODEL;
    float* y = g_x + (size_t)row * DMODEL;
    int t = threadIdx.x;

    float v0 = x[t], v1 = x[t + 256], v2 = x[t + 512];
    float s  = v0 + v1 + v2;
    float q  = v0*v0 + v1*v1 + v2*v2;

    __shared__ float ss[8], sq[8];
    #pragma unroll
    for (int o = 16; o > 0; o >>= 1) {
        s += __shfl_xor_sync(0xffffffffu, s, o);
        q += __shfl_xor_sync(0xffffffffu, q, o);
    }
    if ((t & 31) == 0) { ss[t >> 5] = s; sq[t >> 5] = q; }
    __syncthreads();
    if (t == 0) {
        float a = 0.f, b2 = 0.f;
        #pragma unroll
        for (int i = 0; i < 8; i++) { a += ss[i]; b2 += sq[i]; }
        ss[0] = a; sq[0] = b2;
    }
    __syncthreads();
    float mean = ss[0] * (1.0f / DMODEL);
    float var  = sq[0] * (1.0f / DMODEL) - mean * mean;
    float inv  = rsqrtf(var + 1e-5f);

    y[t]       = (v0 - mean) * inv * gamma[t]       + beta[t];
    y[t + 256] = (v1 - mean) * inv * gamma[t + 256] + beta[t + 256];
    y[t + 512] = (v2 - mean) * inv * gamma[t + 512] + beta[t + 512];
}

// ---------------- patch bins (exact replica of reference semantics) ----------------
__global__ void bins_kernel(
    const float* __restrict__ boxes,
    const int* __restrict__ image_sizes)
{
    int idx = blockIdx.x * blockDim.x + threadIdx.x;
    if (idx >= BATCH * SEQ) return;
    int b = idx / SEQ;
    float w = (float)image_sizes[b * 4 + 0];
    float h = (float)image_sizes[b * 4 + 1];
    const float* bx = boxes + (size_t)idx * 4;
    float x0 = bx[0] * w, y0 = bx[1] * h, x1 = bx[2] * w, y1 = bx[3] * h;
    float spaw = floorf(w / 11.0f);
    float spah = floorf(h / 11.0f);
    float cx = floorf((x0 + x1) / 2.0f);
    float cy = floorf((y0 + y1) / 2.0f);
    int pxv = 0, pyv = 0;
    for (int j = 10; j >= 0; j--) {
        float lbw = (float)j * spaw, hbw = (float)(j + 1) * spaw;
        if (lbw <= cx && cx <= hbw) pxv = j;
        float lbh = (float)j * spah, hbh = (float)(j + 1) * spah;
        if (lbh <= cy && cy <= hbh) pyv = j;
    }
    g_px[idx] = pxv;
    g_py[idx] = pyv;
}

// ---------------- bf16 3x helpers ----------------
__device__ __forceinline__ void bf16_split(float v, __nv_bfloat16& h, __nv_bfloat16& l)
{
    h = __float2bfloat16_rn(v);
    l = __float2bfloat16_rn(v - __bfloat162float(h));
}

__device__ __forceinline__ unsigned bf16pack(__nv_bfloat16 a, __nv_bfloat16 b)
{
    __nv_bfloat162 p = __halves2bfloat162(a, b);   // .x (low) = even-k
    return *reinterpret_cast<unsigned*>(&p);
}

__device__ __forceinline__ void split2(float f0, float f1, unsigned& hi, unsigned& lo)
{
    __nv_bfloat16 h0,l0,h1,l1;
    bf16_split(f0, h0, l0); bf16_split(f1, h1, l1);
    hi = bf16pack(h0, h1); lo = bf16pack(l0, l1);
}

template<int STR>
__device__ __forceinline__ void store_row_bf16(
    unsigned (*Hi)[STR], unsigned (*Lo)[STR], int kp0, int m, float4 v)
{
    unsigned h01, l01, h23, l23;
    split2(v.x, v.y, h01, l01);
    split2(v.z, v.w, h23, l23);
    Hi[kp0    ][m] = h01; Lo[kp0    ][m] = l01;
    Hi[kp0 + 1][m] = h23; Lo[kp0 + 1][m] = l23;
}

#define MMA_BF16(D, A, B0, B1)                                                   \
    asm volatile("mma.sync.aligned.m16n8k16.row.col.f32.bf16.bf16.f32 "          \
                 "{%0,%1,%2,%3},{%4,%5,%6,%7},{%8,%9},{%0,%1,%2,%3};"            \
                 : "+f"(D[0]), "+f"(D[1]), "+f"(D[2]), "+f"(D[3])                \
                 : "r"(A[0]), "r"(A[1]), "r"(A[2]), "r"(A[3]), "r"(B0), "r"(B1))

// ---------------- shared GEMM body (3xBF16, NT, 128x128 tile) ----------------
template<int SCATTER>
__device__ __forceinline__ void gemm_body(
    const float* __restrict__ A, const float* __restrict__ W,
    const float* __restrict__ bias, float* __restrict__ Cdst,
    int row0, int col0)
{
    const int K = DMODEL;
    __shared__ unsigned As_hi[2][8][136], As_lo[2][8][136];
    __shared__ unsigned Ws_hi[2][8][136], Ws_lo[2][8][136];

    const int t    = threadIdx.x;
    const int lane = t & 31;
    const int wid  = t >> 5;
    const int warp_m = wid & 3;
    const int warp_n = wid >> 2;
    const int r = lane >> 2;
    const int c = lane & 3;

    const int fm = t >> 2;
    const int kq = (t & 3) * 4;
    const int kp0 = (t & 3) * 2;

    const float* Ap = A + (size_t)(row0 + fm) * K + kq;
    const float* Wp = W + (size_t)(col0 + fm) * K + kq;

    float d[2][8][4];
    #pragma unroll
    for (int i = 0; i < 2; i++)
        #pragma unroll
        for (int j = 0; j < 8; j++)
            #pragma unroll
            for (int e = 0; e < 4; e++) d[i][j][e] = 0.f;

    float4 aR0 = *(const float4*)(Ap);
    float4 aR1 = *(const float4*)(Ap + (size_t)64 * K);
    float4 wR0 = *(const float4*)(Wp);
    float4 wR1 = *(const float4*)(Wp + (size_t)64 * K);

    store_row_bf16<136>(As_hi[0], As_lo[0], kp0, fm,      aR0);
    store_row_bf16<136>(As_hi[0], As_lo[0], kp0, fm + 64, aR1);
    store_row_bf16<136>(Ws_hi[0], Ws_lo[0], kp0, fm,      wR0);
    store_row_bf16<136>(Ws_hi[0], Ws_lo[0], kp0, fm + 64, wR1);
    __syncthreads();

    const int NIT = K / 16;
    for (int it = 0; it < NIT; it++) {
        const int buf = it & 1;
        if (it + 1 < NIT) {
            int k0 = (it + 1) * 16;
            aR0 = *(const float4*)(Ap + k0);
            aR1 = *(const float4*)(Ap + (size_t)64 * K + k0);
            wR0 = *(const float4*)(Wp + k0);
            wR1 = *(const float4*)(Wp + (size_t)64 * K + k0);
        }
        {
            unsigned (*Ah)[136] = As_hi[buf];
            unsigned (*Al)[136] = As_lo[buf];
            unsigned (*Wh)[136] = Ws_hi[buf];
            unsigned (*Wl)[136] = Ws_lo[buf];

            unsigned ah[2][4], al[2][4];
            #pragma unroll
            for (int mt = 0; mt < 2; mt++) {
                int rb = warp_m * 32 + mt * 16 + r;
                ah[mt][0] = Ah[c][rb];     ah[mt][1] = Ah[c][rb + 8];
                ah[mt][2] = Ah[c + 4][rb]; ah[mt][3] = Ah[c + 4][rb + 8];
                al[mt][0] = Al[c][rb];     al[mt][1] = Al[c][rb + 8];
                al[mt][2] = Al[c + 4][rb]; al[mt][3] = Al[c + 4][rb + 8];
            }
            #pragma unroll
            for (int nt = 0; nt < 8; nt++) {
                int nb = warp_n * 64 + nt * 8 + r;
                unsigned b0h = Wh[c][nb], b1h = Wh[c + 4][nb];
                unsigned b0l = Wl[c][nb], b1l = Wl[c + 4][nb];
                #pragma unroll
                for (int mt = 0; mt < 2; mt++) {
                    MMA_BF16(d[mt][nt], ah[mt], b0h, b1h);
                    MMA_BF16(d[mt][nt], ah[mt], b0l, b1l);
                    MMA_BF16(d[mt][nt], al[mt], b0h, b1h);
                }
            }
        }
        if (it + 1 < NIT) {
            int nb = buf ^ 1;
            store_row_bf16<136>(As_hi[nb], As_lo[nb], kp0, fm,      aR0);
            store_row_bf16<136>(As_hi[nb], As_lo[nb], kp0, fm + 64, aR1);
            store_row_bf16<136>(Ws_hi[nb], Ws_lo[nb], kp0, fm,      wR0);
            store_row_bf16<136>(Ws_hi[nb], Ws_lo[nb], kp0, fm + 64, wR1);
        }
        __syncthreads();
    }

    #pragma unroll
    for (int mt = 0; mt < 2; mt++) {
        int m0 = row0 + warp_m * 32 + mt * 16 + r;
        #pragma unroll
        for (int nt = 0; nt < 8; nt++) {
            int n = col0 + warp_n * 64 + nt * 8 + 2 * c;
            float b0v = bias[n], b1v = bias[n + 1];
            float v00 = d[mt][nt][0] + b0v, v01 = d[mt][nt][1] + b1v;
            float v10 = d[mt][nt][2] + b0v, v11 = d[mt][nt][3] + b1v;
            if (SCATTER == 0) {
                *(float2*)&Cdst[(size_t)m0 * DMODEL + n]       = make_float2(v00, v01);
                *(float2*)&Cdst[(size_t)(m0 + 8) * DMODEL + n] = make_float2(v10, v11);
            } else {
                int hh = n >> 6, dk = n & 63;
                int b1_ = m0 >> 9,       nq1 = m0 & 511;
                int b2_ = (m0 + 8) >> 9, nq2 = (m0 + 8) & 511;
                *(float2*)&Cdst[(((size_t)(b1_ * NHEAD + hh)) * SEQ + nq1) * DHEAD + dk] = make_float2(v00, v01);
                *(float2*)&Cdst[(((size_t)(b2_ * NHEAD + hh)) * SEQ + nq2) * DHEAD + dk] = make_float2(v10, v11);
            }
        }
    }
}

__global__ __launch_bounds__(256) void gemm_qkv(
    const float* __restrict__ Wq, const float* __restrict__ Wk, const float* __restrict__ Wv,
    const float* __restrict__ bq, const float* __restrict__ bk, const float* __restrict__ bv)
{
    const float* W    = (blockIdx.z == 0) ? Wq : (blockIdx.z == 1) ? Wk : Wv;
    const float* bias = (blockIdx.z == 0) ? bq : (blockIdx.z == 1) ? bk : bv;
    float* Cdst       = (blockIdx.z == 0) ? g_q : (blockIdx.z == 1) ? g_k : g_v;
    gemm_body<1>(g_x, W, bias, Cdst, blockIdx.y * 128, blockIdx.x * 128);
}

__global__ __launch_bounds__(256) void gemm_out(
    const float* __restrict__ Wo, const float* __restrict__ bo, float* __restrict__ out)
{
    gemm_body<0>(g_ctx, Wo, bo, out, blockIdx.y * 128, blockIdx.x * 128);
}

// ---------------- fused attention ----------------
// grid (q-tile=8, bh=192), 512 threads = 16 warps.
// S row layout (516 x u32/f32 per row): phase 1/2 use rows as 512 fp32 scores;
// during softmax each row is repacked IN PLACE: hi words at [0..255], lo at [258..513].
#define SSTR     516
#define SM_S     0                                      // 64*516*4 = 132096 B
#define SM_QHI   132096                                 // unsigned Qhi[32][72]  9216 B
#define SM_QLO   141312                                 // unsigned Qlo[32][72]  9216 B
#define SM_KHI   150528                                 // unsigned Khi[32][72]  9216 B (also Vhi)
#define SM_KLO   159744                                 // unsigned Klo[32][72]  9216 B (also Vlo)
#define SM_EMB   168960                                 // float emb[32]          128 B
#define SM_PXQ   169088                                 // int spxq[64]           256 B
#define SM_PYQ   169344                                 // int spyq[64]           256 B
#define SM_PXK   169600                                 // int spxk[512]         2048 B
#define SM_PYK   171648                                 // int spyk[512]         2048 B
#define SMEM_ATTN 173696

__global__ __launch_bounds__(512) void fused_attn(
    const float* __restrict__ dist_emb, float* __restrict__ att)
{
    extern __shared__ char smraw[];
    float    (*S)[SSTR]  = (float(*)[SSTR])   (smraw + SM_S);
    unsigned (*Su)[SSTR] = (unsigned(*)[SSTR])(smraw + SM_S);
    unsigned (*Qhi)[72]  = (unsigned(*)[72])(smraw + SM_QHI);
    unsigned (*Qlo)[72]  = (unsigned(*)[72])(smraw + SM_QLO);
    unsigned (*Khi)[72]  = (unsigned(*)[72])(smraw + SM_KHI);
    unsigned (*Klo)[72]  = (unsigned(*)[72])(smraw + SM_KLO);
    float*   emb  = (float*)(smraw + SM_EMB);
    int*     spxq = (int*)  (smraw + SM_PXQ);
    int*     spyq = (int*)  (smraw + SM_PYQ);
    int*     spxk = (int*)  (smraw + SM_PXK);
    int*     spyk = (int*)  (smraw + SM_PYK);

    const int t    = threadIdx.x;
    const int lane = t & 31;
    const int wid  = t >> 5;          // 0..15
    const int warp_m = wid & 3;       // rows warp_m*16 + {r, r+8}
    const int warp_n = wid >> 2;      // 16 cols each
    const int r = lane >> 2;          // 0..7
    const int c = lane & 3;           // 0..3

    const int bh = blockIdx.y;
    const int b  = bh / NHEAD, h = bh % NHEAD;
    const int q0 = blockIdx.x * 64;

    const float* Qb = g_q + (size_t)bh * SEQ * DHEAD;
    const float* Kb = g_k + (size_t)bh * SEQ * DHEAD;
    const float* Vb = g_v + (size_t)bh * SEQ * DHEAD;

    // ---- preload tables + Q tile ----
    if (t < NDIST) emb[t] = dist_emb[t * NHEAD + h];
    if (t < 64) {
        spxq[t] = g_px[b * SEQ + q0 + t];
        spyq[t] = g_py[b * SEQ + q0 + t];
    }
    spxk[t] = g_px[b * SEQ + t];
    spyk[t] = g_py[b * SEQ + t];

    const int frow = t >> 3;          // 0..63
    const int fcq  = (t & 7) * 8;     // 0..56
    const int fkp0 = (t & 7) * 4;
    {
        const float* qp = Qb + (size_t)(q0 + frow) * DHEAD + fcq;
        #pragma unroll
        for (int u = 0; u < 2; u++) {
            float4 v = *(const float4*)(qp + u * 4);
            store_row_bf16<72>(Qhi, Qlo, fkp0 + u * 2, frow, v);
        }
    }
    __syncthreads();

    // ---- Q fragments (registers, reused 8x) ----
    const int rb = warp_m * 16 + r;
    unsigned qah[4][4], qal[4][4];
    #pragma unroll
    for (int ks = 0; ks < 4; ks++) {
        qah[ks][0] = Qhi[ks * 8 + c][rb];     qah[ks][1] = Qhi[ks * 8 + c][rb + 8];
        qah[ks][2] = Qhi[ks * 8 + c + 4][rb]; qah[ks][3] = Qhi[ks * 8 + c + 4][rb + 8];
        qal[ks][0] = Qlo[ks * 8 + c][rb];     qal[ks][1] = Qlo[ks * 8 + c][rb + 8];
        qal[ks][2] = Qlo[ks * 8 + c + 4][rb]; qal[ks][3] = Qlo[ks * 8 + c + 4][rb + 8];
    }

    // ---- phase 1: S = QK^T/8 + bias ----
    for (int kt = 0; kt < 8; kt++) {
        float4 kv[2];
        {
            const float* kp = Kb + (size_t)(kt * 64 + frow) * DHEAD + fcq;
            #pragma unroll
            for (int u = 0; u < 2; u++) kv[u] = *(const float4*)(kp + u * 4);
        }
        __syncthreads();
        #pragma unroll
        for (int u = 0; u < 2; u++)
            store_row_bf16<72>(Khi, Klo, fkp0 + u * 2, frow, kv[u]);
        __syncthreads();

        float d[2][4];
        #pragma unroll
        for (int nt = 0; nt < 2; nt++)
            #pragma unroll
            for (int e = 0; e < 4; e++) d[nt][e] = 0.f;

        #pragma unroll
        for (int ks = 0; ks < 4; ks++) {
            #pragma unroll
            for (int nt = 0; nt < 2; nt++) {
                int nb = warp_n * 16 + nt * 8 + r;
                unsigned b0h = Khi[ks * 8 + c][nb], b1h = Khi[ks * 8 + c + 4][nb];
                unsigned b0l = Klo[ks * 8 + c][nb], b1l = Klo[ks * 8 + c + 4][nb];
                MMA_BF16(d[nt], qah[ks], b0h, b1h);
                MMA_BF16(d[nt], qah[ks], b0l, b1l);
                MMA_BF16(d[nt], qal[ks], b0h, b1h);
            }
        }

        int pxq0 = spxq[rb],     pyq0 = spyq[rb];
        int pxq1 = spxq[rb + 8], pyq1 = spyq[rb + 8];
        #pragma unroll
        for (int nt = 0; nt < 2; nt++) {
            int ncol = warp_n * 16 + nt * 8 + 2 * c;
            int kg   = kt * 64 + ncol;
            int pxk0 = spxk[kg],     pyk0 = spyk[kg];
            int pxk1 = spxk[kg + 1], pyk1 = spyk[kg + 1];
            int dx00 = pxk0 - pxq0, dy00 = pyk0 - pyq0;
            int dx01 = pxk1 - pxq0, dy01 = pyk1 - pyq0;
            int dx10 = pxk0 - pxq1, dy10 = pyk0 - pyq1;
            int dx11 = pxk1 - pxq1, dy11 = pyk1 - pyq1;
            float e00 = emb[(int)(sqrtf((float)(dx00*dx00 + dy00*dy00)) * 2.0f)];
            float e01 = emb[(int)(sqrtf((float)(dx01*dx01 + dy01*dy01)) * 2.0f)];
            float e10 = emb[(int)(sqrtf((float)(dx10*dx10 + dy10*dy10)) * 2.0f)];
            float e11 = emb[(int)(sqrtf((float)(dx11*dx11 + dy11*dy11)) * 2.0f)];
            S[rb][kg]         = d[nt][0] * 0.125f + e00;
            S[rb][kg + 1]     = d[nt][1] * 0.125f + e01;
            S[rb + 8][kg]     = d[nt][2] * 0.125f + e10;
            S[rb + 8][kg + 1] = d[nt][3] * 0.125f + e11;
        }
    }
    __syncthreads();

    // ---- phase 2: softmax (warp x 4 rows), write att, repack row to bf16 hi/lo in place ----
    for (int rr = 0; rr < 4; rr++) {
        int row = wid * 4 + rr;
        float* Sr = S[row];
        float4 x0 = ((float4*)Sr)[lane];
        float4 x1 = ((float4*)Sr)[lane + 32];
        float4 x2 = ((float4*)Sr)[lane + 64];
        float4 x3 = ((float4*)Sr)[lane + 96];
        float m = fmaxf(fmaxf(fmaxf(x0.x,x0.y),fmaxf(x0.z,x0.w)),
                  fmaxf(fmaxf(fmaxf(x1.x,x1.y),fmaxf(x1.z,x1.w)),
                  fmaxf(fmaxf(fmaxf(x2.x,x2.y),fmaxf(x2.z,x2.w)),
                        fmaxf(fmaxf(x3.x,x3.y),fmaxf(x3.z,x3.w)))));
        #pragma unroll
        for (int o = 16; o > 0; o >>= 1) m = fmaxf(m, __shfl_xor_sync(0xffffffffu, m, o));
        x0.x = __expf(x0.x - m); x0.y = __expf(x0.y - m); x0.z = __expf(x0.z - m); x0.w = __expf(x0.w - m);
        x1.x = __expf(x1.x - m); x1.y = __expf(x1.y - m); x1.z = __expf(x1.z - m); x1.w = __expf(x1.w - m);
        x2.x = __expf(x2.x - m); x2.y = __expf(x2.y - m); x2.z = __expf(x2.z - m); x2.w = __expf(x2.w - m);
        x3.x = __expf(x3.x - m); x3.y = __expf(x3.y - m); x3.z = __expf(x3.z - m); x3.w = __expf(x3.w - m);
        float s = (x0.x+x0.y+x0.z+x0.w) + (x1.x+x1.y+x1.z+x1.w)
                + (x2.x+x2.y+x2.z+x2.w) + (x3.x+x3.y+x3.z+x3.w);
        #pragma unroll
        for (int o = 16; o > 0; o >>= 1) s += __shfl_xor_sync(0xffffffffu, s, o);
        float inv = 1.0f / s;
        x0.x*=inv; x0.y*=inv; x0.z*=inv; x0.w*=inv;
        x1.x*=inv; x1.y*=inv; x1.z*=inv; x1.w*=inv;
        x2.x*=inv; x2.y*=inv; x2.z*=inv; x2.w*=inv;
        x3.x*=inv; x3.y*=inv; x3.z*=inv; x3.w*=inv;

        float* ar = att + ((size_t)bh * SEQ + q0 + row) * SEQ;
        ((float4*)ar)[lane]      = x0;
        ((float4*)ar)[lane + 32] = x1;
        ((float4*)ar)[lane + 64] = x2;
        ((float4*)ar)[lane + 96] = x3;

        // repack in place: hi words [0..255], lo words [258..513] (u32 indices)
        unsigned* Sru = (unsigned*)Sr;
        uint2 wh, wl;
        split2(x0.x, x0.y, wh.x, wl.x); split2(x0.z, x0.w, wh.y, wl.y);
        *(uint2*)&Sru[lane * 2]            = wh;
        *(uint2*)&Sru[258 + lane * 2]      = wl;
        split2(x1.x, x1.y, wh.x, wl.x); split2(x1.z, x1.w, wh.y, wl.y);
        *(uint2*)&Sru[64 + lane * 2]       = wh;
        *(uint2*)&Sru[258 + 64 + lane * 2] = wl;
        split2(x2.x, x2.y, wh.x, wl.x); split2(x2.z, x2.w, wh.y, wl.y);
        *(uint2*)&Sru[128 + lane * 2]      = wh;
        *(uint2*)&Sru[258 + 128 + lane * 2]= wl;
        split2(x3.x, x3.y, wh.x, wl.x); split2(x3.z, x3.w, wh.y, wl.y);
        *(uint2*)&Sru[192 + lane * 2]      = wh;
        *(uint2*)&Sru[258 + 192 + lane * 2]= wl;
    }
    __syncthreads();

    // ---- phase 3: ctx = P @ V (A fragments loaded directly as packed bf16) ----
    unsigned (*Vhi)[72] = Khi;
    unsigned (*Vlo)[72] = Klo;
    float ctx[2][4];
    #pragma unroll
    for (int nt = 0; nt < 2; nt++)
        #pragma unroll
        for (int e = 0; e < 4; e++) ctx[nt][e] = 0.f;

    const int vkp = t >> 4;           // 0..31 (key pair within tile)
    const int vd0 = (t & 15) * 4;     // 0..60 (head-dim quad)

    for (int kt = 0; kt < 8; kt++) {
        float4 v0, v1;
        {
            const float* vp = Vb + (size_t)(kt * 64 + 2 * vkp) * DHEAD + vd0;
            v0 = *(const float4*)(vp);
            v1 = *(const float4*)(vp + DHEAD);
        }
        __syncthreads();   // prior mma done reading Vhi
        {
            unsigned hi, lo;
            split2(v0.x, v1.x, hi, lo); Vhi[vkp][vd0]     = hi; Vlo[vkp][vd0]     = lo;
            split2(v0.y, v1.y, hi, lo); Vhi[vkp][vd0 + 1] = hi; Vlo[vkp][vd0 + 1] = lo;
            split2(v0.z, v1.z, hi, lo); Vhi[vkp][vd0 + 2] = hi; Vlo[vkp][vd0 + 2] = lo;
            split2(v0.w, v1.w, hi, lo); Vhi[vkp][vd0 + 3] = hi; Vlo[vkp][vd0 + 3] = lo;
        }
        __syncthreads();

        #pragma unroll
        for (int ks = 0; ks < 4; ks++) {
            int kbp = kt * 32 + ks * 8;     // kpair base within S rows
            unsigned ah[4], al[4];
            ah[0] = Su[rb][kbp + c];           ah[1] = Su[rb + 8][kbp + c];
            ah[2] = Su[rb][kbp + c + 4];       ah[3] = Su[rb + 8][kbp + c + 4];
            al[0] = Su[rb][258 + kbp + c];     al[1] = Su[rb + 8][258 + kbp + c];
            al[2] = Su[rb][258 + kbp + c + 4]; al[3] = Su[rb + 8][258 + kbp + c + 4];
            #pragma unroll
            for (int nt = 0; nt < 2; nt++) {
                int nb = warp_n * 16 + nt * 8 + r;
                unsigned b0h = Vhi[ks * 8 + c][nb], b1h = Vhi[ks * 8 + c + 4][nb];
                unsigned b0l = Vlo[ks * 8 + c][nb], b1l = Vlo[ks * 8 + c + 4][nb];
                MMA_BF16(ctx[nt], ah, b0h, b1h);
                MMA_BF16(ctx[nt], ah, b0l, b1l);
                MMA_BF16(ctx[nt], al, b0h, b1h);
            }
        }
    }

    // ---- epilogue ----
    #pragma unroll
    for (int nt = 0; nt < 2; nt++) {
        int q1 = q0 + rb;
        int dcol = warp_n * 16 + nt * 8 + 2 * c;
        *(float2*)&g_ctx[((size_t)(b * SEQ + q1)) * DMODEL + h * DHEAD + dcol] =
            make_float2(ctx[nt][0], ctx[nt][1]);
        *(float2*)&g_ctx[((size_t)(b * SEQ + q1 + 8)) * DMODEL + h * DHEAD + dcol] =
            make_float2(ctx[nt][2], ctx[nt][3]);
    }
}

// ---------------- launch ----------------
extern "C" void kernel_launch(void* const* d_in, const int* in_sizes, int n_in,
                              void* d_out, int out_size)
{
    const float* features    = (const float*)d_in[0];
    const float* boxes       = (const float*)d_in[1];
    const int*   image_sizes = (const int*)  d_in[2];
    const float* Wq    = (const float*)d_in[3];
    const float* bq    = (const float*)d_in[4];
    const float* Wk    = (const float*)d_in[5];
    const float* bk    = (const float*)d_in[6];
    const float* Wv    = (const float*)d_in[7];
    const float* bv    = (const float*)d_in[8];
    const float* Wo    = (const float*)d_in[9];
    const float* bo    = (const float*)d_in[10];
    const float* gamma = (const float*)d_in[11];
    const float* beta  = (const float*)d_in[12];
    const float* demb  = (const float*)d_in[13];

    float* out = (float*)d_out;
    float* att = out + (size_t)BATCH * SEQ * DMODEL;

    cudaFuncSetAttribute(fused_attn, cudaFuncAttributeMaxDynamicSharedMemorySize, SMEM_ATTN);

    const int M = BATCH * SEQ;   // 8192

    ln_kernel<<<M, 256>>>(features, gamma, beta);
    bins_kernel<<<(M + 255) / 256, 256>>>(boxes, image_sizes);

    gemm_qkv<<<dim3(DMODEL / 128, M / 128, 3), 256>>>(Wq, Wk, Wv, bq, bk, bv);

    fused_attn<<<dim3(SEQ / 64, BATCH * NHEAD), 512, SMEM_ATTN>>>(demb, att);

    gemm_out<<<dim3(DMODEL / 128, M / 128), 256>>>(Wo, bo, out);
}

// round 14
// speedup vs baseline: 2.2725x; 1.0151x over previous
#include <cuda_runtime.h>
#include <cuda_bf16.h>
#include <math.h>

#define BATCH  16
#define SEQ    512
#define DMODEL 768
#define NHEAD  12
#define DHEAD  64
#define NDIST  32

// ---------------- scratch (static device memory; referenced by symbol only) ----------------
__device__ float g_x  [BATCH*SEQ*DMODEL];
__device__ float g_q  [BATCH*SEQ*DMODEL];   // layout (B,H,N,DK)
__device__ float g_k  [BATCH*SEQ*DMODEL];   // layout (B,H,N,DK)
__device__ float g_v  [BATCH*SEQ*DMODEL];   // layout (B,H,N,DK)
__device__ float g_ctx[BATCH*SEQ*DMODEL];   // layout (B,N,H*DK)
__device__ int   g_px [BATCH*SEQ];
__device__ int   g_py [BATCH*SEQ];

// ---------------- LayerNorm ----------------
__global__ __launch_bounds__(256) void ln_kernel(
    const float* __restrict__ feat,
    const float* __restrict__ gamma,
    const float* __restrict__ beta)
{
    int row = blockIdx.x;
    const float* x = feat + (size_t)row * DMODEL;
    float* y = g_x + (size_t)row * DMODEL;
    int t = threadIdx.x;

    float v0 = x[t], v1 = x[t + 256], v2 = x[t + 512];
    float s  = v0 + v1 + v2;
    float q  = v0*v0 + v1*v1 + v2*v2;

    __shared__ float ss[8], sq[8];
    #pragma unroll
    for (int o = 16; o > 0; o >>= 1) {
        s += __shfl_xor_sync(0xffffffffu, s, o);
        q += __shfl_xor_sync(0xffffffffu, q, o);
    }
    if ((t & 31) == 0) { ss[t >> 5] = s; sq[t >> 5] = q; }
    __syncthreads();
    if (t == 0) {
        float a = 0.f, b2 = 0.f;
        #pragma unroll
        for (int i = 0; i < 8; i++) { a += ss[i]; b2 += sq[i]; }
        ss[0] = a; sq[0] = b2;
    }
    __syncthreads();
    float mean = ss[0] * (1.0f / DMODEL);
    float var  = sq[0] * (1.0f / DMODEL) - mean * mean;
    float inv  = rsqrtf(var + 1e-5f);

    y[t]       = (v0 - mean) * inv * gamma[t]       + beta[t];
    y[t + 256] = (v1 - mean) * inv * gamma[t + 256] + beta[t + 256];
    y[t + 512] = (v2 - mean) * inv * gamma[t + 512] + beta[t + 512];
}

// ---------------- patch bins (exact replica of reference semantics) ----------------
__global__ void bins_kernel(
    const float* __restrict__ boxes,
    const int* __restrict__ image_sizes)
{
    int idx = blockIdx.x * blockDim.x + threadIdx.x;
    if (idx >= BATCH * SEQ) return;
    int b = idx / SEQ;
    float w = (float)image_sizes[b * 4 + 0];
    float h = (float)image_sizes[b * 4 + 1];
    const float* bx = boxes + (size_t)idx * 4;
    float x0 = bx[0] * w, y0 = bx[1] * h, x1 = bx[2] * w, y1 = bx[3] * h;
    float spaw = floorf(w / 11.0f);
    float spah = floorf(h / 11.0f);
    float cx = floorf((x0 + x1) / 2.0f);
    float cy = floorf((y0 + y1) / 2.0f);
    int pxv = 0, pyv = 0;
    for (int j = 10; j >= 0; j--) {
        float lbw = (float)j * spaw, hbw = (float)(j + 1) * spaw;
        if (lbw <= cx && cx <= hbw) pxv = j;
        float lbh = (float)j * spah, hbh = (float)(j + 1) * spah;
        if (lbh <= cy && cy <= hbh) pyv = j;
    }
    g_px[idx] = pxv;
    g_py[idx] = pyv;
}

// ---------------- bf16 3x helpers ----------------
__device__ __forceinline__ void bf16_split(float v, __nv_bfloat16& h, __nv_bfloat16& l)
{
    h = __float2bfloat16_rn(v);
    l = __float2bfloat16_rn(v - __bfloat162float(h));
}

__device__ __forceinline__ unsigned bf16pack(__nv_bfloat16 a, __nv_bfloat16 b)
{
    __nv_bfloat162 p = __halves2bfloat162(a, b);   // .x (low) = even-k
    return *reinterpret_cast<unsigned*>(&p);
}

__device__ __forceinline__ void split2(float f0, float f1, unsigned& hi, unsigned& lo)
{
    __nv_bfloat16 h0,l0,h1,l1;
    bf16_split(f0, h0, l0); bf16_split(f1, h1, l1);
    hi = bf16pack(h0, h1); lo = bf16pack(l0, l1);
}

template<int STR>
__device__ __forceinline__ void store_row_bf16(
    unsigned (*Hi)[STR], unsigned (*Lo)[STR], int kp0, int m, float4 v)
{
    unsigned h01, l01, h23, l23;
    split2(v.x, v.y, h01, l01);
    split2(v.z, v.w, h23, l23);
    Hi[kp0    ][m] = h01; Lo[kp0    ][m] = l01;
    Hi[kp0 + 1][m] = h23; Lo[kp0 + 1][m] = l23;
}

#define MMA_BF16(D, A, B0, B1)                                                   \
    asm volatile("mma.sync.aligned.m16n8k16.row.col.f32.bf16.bf16.f32 "          \
                 "{%0,%1,%2,%3},{%4,%5,%6,%7},{%8,%9},{%0,%1,%2,%3};"            \
                 : "+f"(D[0]), "+f"(D[1]), "+f"(D[2]), "+f"(D[3])                \
                 : "r"(A[0]), "r"(A[1]), "r"(A[2]), "r"(A[3]), "r"(B0), "r"(B1))

// ---------------- shared GEMM body (3xBF16, NT, 128x128 tile) ----------------
template<int SCATTER>
__device__ __forceinline__ void gemm_body(
    const float* __restrict__ A, const float* __restrict__ W,
    const float* __restrict__ bias, float* __restrict__ Cdst,
    int row0, int col0)
{
    const int K = DMODEL;
    __shared__ unsigned As_hi[2][8][136], As_lo[2][8][136];
    __shared__ unsigned Ws_hi[2][8][136], Ws_lo[2][8][136];

    const int t    = threadIdx.x;
    const int lane = t & 31;
    const int wid  = t >> 5;
    const int warp_m = wid & 3;
    const int warp_n = wid >> 2;
    const int r = lane >> 2;
    const int c = lane & 3;

    const int fm = t >> 2;
    const int kq = (t & 3) * 4;
    const int kp0 = (t & 3) * 2;

    const float* Ap = A + (size_t)(row0 + fm) * K + kq;
    const float* Wp = W + (size_t)(col0 + fm) * K + kq;

    float d[2][8][4];
    #pragma unroll
    for (int i = 0; i < 2; i++)
        #pragma unroll
        for (int j = 0; j < 8; j++)
            #pragma unroll
            for (int e = 0; e < 4; e++) d[i][j][e] = 0.f;

    float4 aR0 = *(const float4*)(Ap);
    float4 aR1 = *(const float4*)(Ap + (size_t)64 * K);
    float4 wR0 = *(const float4*)(Wp);
    float4 wR1 = *(const float4*)(Wp + (size_t)64 * K);

    store_row_bf16<136>(As_hi[0], As_lo[0], kp0, fm,      aR0);
    store_row_bf16<136>(As_hi[0], As_lo[0], kp0, fm + 64, aR1);
    store_row_bf16<136>(Ws_hi[0], Ws_lo[0], kp0, fm,      wR0);
    store_row_bf16<136>(Ws_hi[0], Ws_lo[0], kp0, fm + 64, wR1);
    __syncthreads();

    const int NIT = K / 16;
    for (int it = 0; it < NIT; it++) {
        const int buf = it & 1;
        if (it + 1 < NIT) {
            int k0 = (it + 1) * 16;
            aR0 = *(const float4*)(Ap + k0);
            aR1 = *(const float4*)(Ap + (size_t)64 * K + k0);
            wR0 = *(const float4*)(Wp + k0);
            wR1 = *(const float4*)(Wp + (size_t)64 * K + k0);
        }
        {
            unsigned (*Ah)[136] = As_hi[buf];
            unsigned (*Al)[136] = As_lo[buf];
            unsigned (*Wh)[136] = Ws_hi[buf];
            unsigned (*Wl)[136] = Ws_lo[buf];

            unsigned ah[2][4], al[2][4];
            #pragma unroll
            for (int mt = 0; mt < 2; mt++) {
                int rb = warp_m * 32 + mt * 16 + r;
                ah[mt][0] = Ah[c][rb];     ah[mt][1] = Ah[c][rb + 8];
                ah[mt][2] = Ah[c + 4][rb]; ah[mt][3] = Ah[c + 4][rb + 8];
                al[mt][0] = Al[c][rb];     al[mt][1] = Al[c][rb + 8];
                al[mt][2] = Al[c + 4][rb]; al[mt][3] = Al[c + 4][rb + 8];
            }
            #pragma unroll
            for (int nt = 0; nt < 8; nt++) {
                int nb = warp_n * 64 + nt * 8 + r;
                unsigned b0h = Wh[c][nb], b1h = Wh[c + 4][nb];
                unsigned b0l = Wl[c][nb], b1l = Wl[c + 4][nb];
                #pragma unroll
                for (int mt = 0; mt < 2; mt++) {
                    MMA_BF16(d[mt][nt], ah[mt], b0h, b1h);
                    MMA_BF16(d[mt][nt], ah[mt], b0l, b1l);
                    MMA_BF16(d[mt][nt], al[mt], b0h, b1h);
                }
            }
        }
        if (it + 1 < NIT) {
            int nb = buf ^ 1;
            store_row_bf16<136>(As_hi[nb], As_lo[nb], kp0, fm,      aR0);
            store_row_bf16<136>(As_hi[nb], As_lo[nb], kp0, fm + 64, aR1);
            store_row_bf16<136>(Ws_hi[nb], Ws_lo[nb], kp0, fm,      wR0);
            store_row_bf16<136>(Ws_hi[nb], Ws_lo[nb], kp0, fm + 64, wR1);
        }
        __syncthreads();
    }

    #pragma unroll
    for (int mt = 0; mt < 2; mt++) {
        int m0 = row0 + warp_m * 32 + mt * 16 + r;
        #pragma unroll
        for (int nt = 0; nt < 8; nt++) {
            int n = col0 + warp_n * 64 + nt * 8 + 2 * c;
            float b0v = bias[n], b1v = bias[n + 1];
            float v00 = d[mt][nt][0] + b0v, v01 = d[mt][nt][1] + b1v;
            float v10 = d[mt][nt][2] + b0v, v11 = d[mt][nt][3] + b1v;
            if (SCATTER == 0) {
                *(float2*)&Cdst[(size_t)m0 * DMODEL + n]       = make_float2(v00, v01);
                *(float2*)&Cdst[(size_t)(m0 + 8) * DMODEL + n] = make_float2(v10, v11);
            } else {
                int hh = n >> 6, dk = n & 63;
                int b1_ = m0 >> 9,       nq1 = m0 & 511;
                int b2_ = (m0 + 8) >> 9, nq2 = (m0 + 8) & 511;
                *(float2*)&Cdst[(((size_t)(b1_ * NHEAD + hh)) * SEQ + nq1) * DHEAD + dk] = make_float2(v00, v01);
                *(float2*)&Cdst[(((size_t)(b2_ * NHEAD + hh)) * SEQ + nq2) * DHEAD + dk] = make_float2(v10, v11);
            }
        }
    }
}

__global__ __launch_bounds__(256) void gemm_qkv(
    const float* __restrict__ Wq, const float* __restrict__ Wk, const float* __restrict__ Wv,
    const float* __restrict__ bq, const float* __restrict__ bk, const float* __restrict__ bv)
{
    const float* W    = (blockIdx.z == 0) ? Wq : (blockIdx.z == 1) ? Wk : Wv;
    const float* bias = (blockIdx.z == 0) ? bq : (blockIdx.z == 1) ? bk : bv;
    float* Cdst       = (blockIdx.z == 0) ? g_q : (blockIdx.z == 1) ? g_k : g_v;
    gemm_body<1>(g_x, W, bias, Cdst, blockIdx.y * 128, blockIdx.x * 128);
}

__global__ __launch_bounds__(256) void gemm_out(
    const float* __restrict__ Wo, const float* __restrict__ bo, float* __restrict__ out)
{
    gemm_body<0>(g_ctx, Wo, bo, out, blockIdx.y * 128, blockIdx.x * 128);
}

// ---------------- fused attention ----------------
// grid (q-tile=16 x 32 rows, bh=192), 512 threads = 16 warps (warp_m 0..1, warp_n 0..7).
// ~97KB smem -> 2 CTAs/SM. S rows repacked in place to bf16 hi/lo during softmax.
#define SSTR     516
#define SM_S     0                                      // 32*516*4 = 66048 B
#define SM_QHI   66048                                  // unsigned Qhi[32][40]  5120 B
#define SM_QLO   71168                                  // unsigned Qlo[32][40]  5120 B
#define SM_KHI   76288                                  // unsigned Khi[32][72]  9216 B (also Vhi)
#define SM_KLO   85504                                  // unsigned Klo[32][72]  9216 B (also Vlo)
#define SM_EMB   94720                                  // float emb[32]          128 B
#define SM_PXQ   94848                                  // int spxq[32]           128 B
#define SM_PYQ   94976                                  // int spyq[32]           128 B
#define SM_PXK   95104                                  // int spxk[512]         2048 B
#define SM_PYK   97152                                  // int spyk[512]         2048 B
#define SMEM_ATTN 99200

__global__ __launch_bounds__(512) void fused_attn(
    const float* __restrict__ dist_emb, float* __restrict__ att)
{
    extern __shared__ char smraw[];
    float    (*S)[SSTR]  = (float(*)[SSTR])   (smraw + SM_S);
    unsigned (*Su)[SSTR] = (unsigned(*)[SSTR])(smraw + SM_S);
    unsigned (*Qhi)[40]  = (unsigned(*)[40])(smraw + SM_QHI);
    unsigned (*Qlo)[40]  = (unsigned(*)[40])(smraw + SM_QLO);
    unsigned (*Khi)[72]  = (unsigned(*)[72])(smraw + SM_KHI);
    unsigned (*Klo)[72]  = (unsigned(*)[72])(smraw + SM_KLO);
    float*   emb  = (float*)(smraw + SM_EMB);
    int*     spxq = (int*)  (smraw + SM_PXQ);
    int*     spyq = (int*)  (smraw + SM_PYQ);
    int*     spxk = (int*)  (smraw + SM_PXK);
    int*     spyk = (int*)  (smraw + SM_PYK);

    const int t    = threadIdx.x;
    const int lane = t & 31;
    const int wid  = t >> 5;          // 0..15
    const int warp_m = wid & 1;       // rows warp_m*16 + {r, r+8}
    const int warp_n = wid >> 1;      // 0..7 -> 8 cols each
    const int r = lane >> 2;          // 0..7
    const int c = lane & 3;           // 0..3

    const int bh = blockIdx.y;
    const int b  = bh / NHEAD, h = bh % NHEAD;
    const int q0 = blockIdx.x * 32;

    const float* Qb = g_q + (size_t)bh * SEQ * DHEAD;
    const float* Kb = g_k + (size_t)bh * SEQ * DHEAD;
    const float* Vb = g_v + (size_t)bh * SEQ * DHEAD;

    // ---- preload tables + Q tile ----
    if (t < NDIST) emb[t] = dist_emb[t * NHEAD + h];
    if (t < 32) {
        spxq[t] = g_px[b * SEQ + q0 + t];
        spyq[t] = g_py[b * SEQ + q0 + t];
    }
    spxk[t] = g_px[b * SEQ + t];
    spyk[t] = g_py[b * SEQ + t];

    // Q fill: 32 rows x 64 dim, one float4 per thread
    {
        int frow = t >> 4;            // 0..31
        int fc   = (t & 15) * 4;      // 0..60
        float4 v = *(const float4*)(Qb + (size_t)(q0 + frow) * DHEAD + fc);
        store_row_bf16<40>(Qhi, Qlo, (t & 15) * 2, frow, v);
    }
    __syncthreads();

    // ---- Q fragments (registers, reused 8x) ----
    const int rb = warp_m * 16 + r;
    unsigned qah[4][4], qal[4][4];
    #pragma unroll
    for (int ks = 0; ks < 4; ks++) {
        qah[ks][0] = Qhi[ks * 8 + c][rb];     qah[ks][1] = Qhi[ks * 8 + c][rb + 8];
        qah[ks][2] = Qhi[ks * 8 + c + 4][rb]; qah[ks][3] = Qhi[ks * 8 + c + 4][rb + 8];
        qal[ks][0] = Qlo[ks * 8 + c][rb];     qal[ks][1] = Qlo[ks * 8 + c][rb + 8];
        qal[ks][2] = Qlo[ks * 8 + c + 4][rb]; qal[ks][3] = Qlo[ks * 8 + c + 4][rb + 8];
    }

    const int frow = t >> 3;          // 0..63 (K/V fill rows)
    const int fcq  = (t & 7) * 8;
    const int fkp0 = (t & 7) * 4;

    // ---- phase 1: S = QK^T/8 + bias ----
    for (int kt = 0; kt < 8; kt++) {
        float4 kv[2];
        {
            const float* kp = Kb + (size_t)(kt * 64 + frow) * DHEAD + fcq;
            #pragma unroll
            for (int u = 0; u < 2; u++) kv[u] = *(const float4*)(kp + u * 4);
        }
        __syncthreads();
        #pragma unroll
        for (int u = 0; u < 2; u++)
            store_row_bf16<72>(Khi, Klo, fkp0 + u * 2, frow, kv[u]);
        __syncthreads();

        float d[4];
        d[0] = d[1] = d[2] = d[3] = 0.f;

        #pragma unroll
        for (int ks = 0; ks < 4; ks++) {
            int nb = warp_n * 8 + r;
            unsigned b0h = Khi[ks * 8 + c][nb], b1h = Khi[ks * 8 + c + 4][nb];
            unsigned b0l = Klo[ks * 8 + c][nb], b1l = Klo[ks * 8 + c + 4][nb];
            MMA_BF16(d, qah[ks], b0h, b1h);
            MMA_BF16(d, qah[ks], b0l, b1l);
            MMA_BF16(d, qal[ks], b0h, b1h);
        }

        int pxq0 = spxq[rb],     pyq0 = spyq[rb];
        int pxq1 = spxq[rb + 8], pyq1 = spyq[rb + 8];
        {
            int ncol = warp_n * 8 + 2 * c;
            int kg   = kt * 64 + ncol;
            int pxk0 = spxk[kg],     pyk0 = spyk[kg];
            int pxk1 = spxk[kg + 1], pyk1 = spyk[kg + 1];
            int dx00 = pxk0 - pxq0, dy00 = pyk0 - pyq0;
            int dx01 = pxk1 - pxq0, dy01 = pyk1 - pyq0;
            int dx10 = pxk0 - pxq1, dy10 = pyk0 - pyq1;
            int dx11 = pxk1 - pxq1, dy11 = pyk1 - pyq1;
            float e00 = emb[(int)(sqrtf((float)(dx00*dx00 + dy00*dy00)) * 2.0f)];
            float e01 = emb[(int)(sqrtf((float)(dx01*dx01 + dy01*dy01)) * 2.0f)];
            float e10 = emb[(int)(sqrtf((float)(dx10*dx10 + dy10*dy10)) * 2.0f)];
            float e11 = emb[(int)(sqrtf((float)(dx11*dx11 + dy11*dy11)) * 2.0f)];
            S[rb][kg]         = d[0] * 0.125f + e00;
            S[rb][kg + 1]     = d[1] * 0.125f + e01;
            S[rb + 8][kg]     = d[2] * 0.125f + e10;
            S[rb + 8][kg + 1] = d[3] * 0.125f + e11;
        }
    }
    __syncthreads();

    // ---- phase 2: softmax (warp x 2 rows), write att, repack row to bf16 hi/lo in place ----
    for (int rr = 0; rr < 2; rr++) {
        int row = wid * 2 + rr;
        float* Sr = S[row];
        float4 x0 = ((float4*)Sr)[lane];
        float4 x1 = ((float4*)Sr)[lane + 32];
        float4 x2 = ((float4*)Sr)[lane + 64];
        float4 x3 = ((float4*)Sr)[lane + 96];
        float m = fmaxf(fmaxf(fmaxf(x0.x,x0.y),fmaxf(x0.z,x0.w)),
                  fmaxf(fmaxf(fmaxf(x1.x,x1.y),fmaxf(x1.z,x1.w)),
                  fmaxf(fmaxf(fmaxf(x2.x,x2.y),fmaxf(x2.z,x2.w)),
                        fmaxf(fmaxf(x3.x,x3.y),fmaxf(x3.z,x3.w)))));
        #pragma unroll
        for (int o = 16; o > 0; o >>= 1) m = fmaxf(m, __shfl_xor_sync(0xffffffffu, m, o));
        x0.x = __expf(x0.x - m); x0.y = __expf(x0.y - m); x0.z = __expf(x0.z - m); x0.w = __expf(x0.w - m);
        x1.x = __expf(x1.x - m); x1.y = __expf(x1.y - m); x1.z = __expf(x1.z - m); x1.w = __expf(x1.w - m);
        x2.x = __expf(x2.x - m); x2.y = __expf(x2.y - m); x2.z = __expf(x2.z - m); x2.w = __expf(x2.w - m);
        x3.x = __expf(x3.x - m); x3.y = __expf(x3.y - m); x3.z = __expf(x3.z - m); x3.w = __expf(x3.w - m);
        float s = (x0.x+x0.y+x0.z+x0.w) + (x1.x+x1.y+x1.z+x1.w)
                + (x2.x+x2.y+x2.z+x2.w) + (x3.x+x3.y+x3.z+x3.w);
        #pragma unroll
        for (int o = 16; o > 0; o >>= 1) s += __shfl_xor_sync(0xffffffffu, s, o);
        float inv = 1.0f / s;
        x0.x*=inv; x0.y*=inv; x0.z*=inv; x0.w*=inv;
        x1.x*=inv; x1.y*=inv; x1.z*=inv; x1.w*=inv;
        x2.x*=inv; x2.y*=inv; x2.z*=inv; x2.w*=inv;
        x3.x*=inv; x3.y*=inv; x3.z*=inv; x3.w*=inv;

        float* ar = att + ((size_t)bh * SEQ + q0 + row) * SEQ;
        ((float4*)ar)[lane]      = x0;
        ((float4*)ar)[lane + 32] = x1;
        ((float4*)ar)[lane + 64] = x2;
        ((float4*)ar)[lane + 96] = x3;

        // repack in place: hi words [0..255], lo words [258..513]
        unsigned* Sru = (unsigned*)Sr;
        uint2 wh, wl;
        split2(x0.x, x0.y, wh.x, wl.x); split2(x0.z, x0.w, wh.y, wl.y);
        *(uint2*)&Sru[lane * 2]            = wh;
        *(uint2*)&Sru[258 + lane * 2]      = wl;
        split2(x1.x, x1.y, wh.x, wl.x); split2(x1.z, x1.w, wh.y, wl.y);
        *(uint2*)&Sru[64 + lane * 2]       = wh;
        *(uint2*)&Sru[258 + 64 + lane * 2] = wl;
        split2(x2.x, x2.y, wh.x, wl.x); split2(x2.z, x2.w, wh.y, wl.y);
        *(uint2*)&Sru[128 + lane * 2]      = wh;
        *(uint2*)&Sru[258 + 128 + lane * 2]= wl;
        split2(x3.x, x3.y, wh.x, wl.x); split2(x3.z, x3.w, wh.y, wl.y);
        *(uint2*)&Sru[192 + lane * 2]      = wh;
        *(uint2*)&Sru[258 + 192 + lane * 2]= wl;
    }
    __syncthreads();

    // ---- phase 3: ctx = P @ V ----
    unsigned (*Vhi)[72] = Khi;
    unsigned (*Vlo)[72] = Klo;
    float ctx[4];
    ctx[0] = ctx[1] = ctx[2] = ctx[3] = 0.f;

    const int vkp = t >> 4;           // 0..31 (key pair within tile)
    const int vd0 = (t & 15) * 4;     // 0..60

    for (int kt = 0; kt < 8; kt++) {
        float4 v0, v1;
        {
            const float* vp = Vb + (size_t)(kt * 64 + 2 * vkp) * DHEAD + vd0;
            v0 = *(const float4*)(vp);
            v1 = *(const float4*)(vp + DHEAD);
        }
        __syncthreads();
        {
            unsigned hi, lo;
            split2(v0.x, v1.x, hi, lo); Vhi[vkp][vd0]     = hi; Vlo[vkp][vd0]     = lo;
            split2(v0.y, v1.y, hi, lo); Vhi[vkp][vd0 + 1] = hi; Vlo[vkp][vd0 + 1] = lo;
            split2(v0.z, v1.z, hi, lo); Vhi[vkp][vd0 + 2] = hi; Vlo[vkp][vd0 + 2] = lo;
            split2(v0.w, v1.w, hi, lo); Vhi[vkp][vd0 + 3] = hi; Vlo[vkp][vd0 + 3] = lo;
        }
        __syncthreads();

        #pragma unroll
        for (int ks = 0; ks < 4; ks++) {
            int kbp = kt * 32 + ks * 8;
            unsigned ah[4], al[4];
            ah[0] = Su[rb][kbp + c];           ah[1] = Su[rb + 8][kbp + c];
            ah[2] = Su[rb][kbp + c + 4];       ah[3] = Su[rb + 8][kbp + c + 4];
            al[0] = Su[rb][258 + kbp + c];     al[1] = Su[rb + 8][258 + kbp + c];
            al[2] = Su[rb][258 + kbp + c + 4]; al[3] = Su[rb + 8][258 + kbp + c + 4];
            int nb = warp_n * 8 + r;
            unsigned b0h = Vhi[ks * 8 + c][nb], b1h = Vhi[ks * 8 + c + 4][nb];
            unsigned b0l = Vlo[ks * 8 + c][nb], b1l = Vlo[ks * 8 + c + 4][nb];
            MMA_BF16(ctx, ah, b0h, b1h);
            MMA_BF16(ctx, ah, b0l, b1l);
            MMA_BF16(ctx, al, b0h, b1h);
        }
    }

    // ---- epilogue ----
    {
        int q1 = q0 + rb;
        int dcol = warp_n * 8 + 2 * c;
        *(float2*)&g_ctx[((size_t)(b * SEQ + q1)) * DMODEL + h * DHEAD + dcol] =
            make_float2(ctx[0], ctx[1]);
        *(float2*)&g_ctx[((size_t)(b * SEQ + q1 + 8)) * DMODEL + h * DHEAD + dcol] =
            make_float2(ctx[2], ctx[3]);
    }
}

// ---------------- launch ----------------
extern "C" void kernel_launch(void* const* d_in, const int* in_sizes, int n_in,
                              void* d_out, int out_size)
{
    const float* features    = (const float*)d_in[0];
    const float* boxes       = (const float*)d_in[1];
    const int*   image_sizes = (const int*)  d_in[2];
    const float* Wq    = (const float*)d_in[3];
    const float* bq    = (const float*)d_in[4];
    const float* Wk    = (const float*)d_in[5];
    const float* bk    = (const float*)d_in[6];
    const float* Wv    = (const float*)d_in[7];
    const float* bv    = (const float*)d_in[8];
    const float* Wo    = (const float*)d_in[9];
    const float* bo    = (const float*)d_in[10];
    const float* gamma = (const float*)d_in[11];
    const float* beta  = (const float*)d_in[12];
    const float* demb  = (const float*)d_in[13];

    float* out = (float*)d_out;
    float* att = out + (size_t)BATCH * SEQ * DMODEL;

    cudaFuncSetAttribute(fused_attn, cudaFuncAttributeMaxDynamicSharedMemorySize, SMEM_ATTN);

    const int M = BATCH * SEQ;   // 8192

    ln_kernel<<<M, 256>>>(features, gamma, beta);
    bins_kernel<<<(M + 255) / 256, 256>>>(boxes, image_sizes);

    gemm_qkv<<<dim3(DMODEL / 128, M / 128, 3), 256>>>(Wq, Wk, Wv, bq, bk, bv);

    fused_attn<<<dim3(SEQ / 32, BATCH * NHEAD), 512, SMEM_ATTN>>>(demb, att);

    gemm_out<<<dim3(DMODEL / 128, M / 128), 256>>>(Wo, bo, out);
}